// round 13
// baseline (speedup 1.0000x reference)
#include <cuda_runtime.h>
#include <cuda_fp16.h>

#define C_DIM 192
#define HEADS 6
#define HD 32
#define BATCH 128
#define SEQ 512
#define MROWS (BATCH * SEQ)        // 65536
#define BH (BATCH * HEADS)         // 768
#define LOGIT_MAX 4.6051701859880914f
#define LOG2E 1.4426950408889634f

// ---------------- device-global scratch ----------------
__device__ __half g_qh[(size_t)BH * SEQ * HD];    // normalized * scale * log2e q
__device__ __half g_kh[(size_t)BH * SEQ * HD];    // normalized k
__device__ __half g_vt[(size_t)BH * HD * SEQ];    // v transposed per (b,h): [d][n]
__device__ __half g_attno[(size_t)MROWS * C_DIM];
__device__ __half g_wqh[C_DIM * C_DIM];
__device__ __half g_wkvh[2 * C_DIM * C_DIM];
__device__ __half g_wkvl[2 * C_DIM * C_DIM];
__device__ __half g_wph[C_DIM * C_DIM];

// ---------------- helpers ----------------
__device__ __forceinline__ unsigned smem_u32(const void* p) {
    return (unsigned)__cvta_generic_to_shared(p);
}
__device__ __forceinline__ void ldsm4(unsigned& r0, unsigned& r1, unsigned& r2, unsigned& r3, unsigned a) {
    asm volatile("ldmatrix.sync.aligned.m8n8.x4.shared.b16 {%0,%1,%2,%3},[%4];\n"
                 : "=r"(r0), "=r"(r1), "=r"(r2), "=r"(r3) : "r"(a));
}
__device__ __forceinline__ void mma16816(float* c, unsigned a0, unsigned a1, unsigned a2, unsigned a3,
                                         unsigned b0, unsigned b1) {
    asm volatile("mma.sync.aligned.m16n8k16.row.col.f32.f16.f16.f32 "
                 "{%0,%1,%2,%3},{%4,%5,%6,%7},{%8,%9},{%0,%1,%2,%3};\n"
                 : "+f"(c[0]), "+f"(c[1]), "+f"(c[2]), "+f"(c[3])
                 : "r"(a0), "r"(a1), "r"(a2), "r"(a3), "r"(b0), "r"(b1));
}
__device__ __forceinline__ void split2(float x, float y, __half2& hi, __half2& lo) {
    __half hx = __float2half_rn(x), hy = __float2half_rn(y);
    hi = __halves2half2(hx, hy);
    lo = __floats2half2_rn(x - __half2float(hx), y - __half2float(hy));
}
__device__ __forceinline__ unsigned pack_h2(float a, float b) {
    __half2 t = __floats2half2_rn(a, b);
    return *(unsigned*)&t;
}
__device__ __forceinline__ float ex2(float x) {
    float y;
    asm("ex2.approx.ftz.f32 %0, %1;" : "=f"(y) : "f"(x));
    return y;
}
__device__ __forceinline__ void cpa16(void* s, const void* g) {
    asm volatile("cp.async.ca.shared.global [%0], [%1], 16;\n" :: "r"(smem_u32(s)), "l"(g));
}
__device__ __forceinline__ void cpa_commit() { asm volatile("cp.async.commit_group;\n"); }
__device__ __forceinline__ void cpa_wait1()  { asm volatile("cp.async.wait_group 1;\n"); }
__device__ __forceinline__ void cpa_wait0()  { asm volatile("cp.async.wait_group 0;\n"); }

// ============================================================
// Weight prep: q_w -> hi; kv_w -> hi+lo split; proj_w -> hi.
// blocks: [0,18) q_w, [18,54) kv_w, [54,72) proj_w.
// ============================================================
__global__ __launch_bounds__(256)
void wprep_kernel(const float* __restrict__ qw, const float* __restrict__ kvw,
                  const float* __restrict__ pw)
{
    int blk = blockIdx.x;
    if (blk >= 18 && blk < 54) {            // kv: split
        const int i = (blk - 18) * 256 + threadIdx.x;
        const float4 a = *(const float4*)&kvw[(size_t)i * 8];
        const float4 b = *(const float4*)&kvw[(size_t)i * 8 + 4];
        __half2 h[4], l[4];
        split2(a.x, a.y, h[0], l[0]);
        split2(a.z, a.w, h[1], l[1]);
        split2(b.x, b.y, h[2], l[2]);
        split2(b.z, b.w, h[3], l[3]);
        *(uint4*)&g_wkvh[(size_t)i * 8] = *(uint4*)h;
        *(uint4*)&g_wkvl[(size_t)i * 8] = *(uint4*)l;
    } else {                                 // q / proj: plain fp16
        const float* src;  __half* dst;
        if (blk < 18) { src = qw; dst = g_wqh; }
        else          { src = pw; dst = g_wph; blk -= 54; }
        const int i = blk * 256 + threadIdx.x;
        const float4 a = *(const float4*)&src[(size_t)i * 8];
        const float4 b = *(const float4*)&src[(size_t)i * 8 + 4];
        __half2 h[4];
        h[0] = __floats2half2_rn(a.x, a.y);
        h[1] = __floats2half2_rn(a.z, a.w);
        h[2] = __floats2half2_rn(b.x, b.y);
        h[3] = __floats2half2_rn(b.z, b.w);
        *(uint4*)&dst[(size_t)i * 8] = *(uint4*)h;
    }
}

// ============================================================
// Tensor-core GEMM. BM=128, BN=64, BK=32, 8 warps.
// MODE 3: fused q+kv, A = fp32 x1/x2 converted in-register
//         (LDG float4 -> half2 -> STS, register double buffer).
//   bx<3:  q  (x1 @ wqh, 1-term)  -> +q_b, L2-norm, *exp(ls)*log2e -> g_qh
//   bx 3-5: k (x2 @ wkvh+wkvl, 2-term) -> L2-norm -> g_kh
//   bx 6-8: v (x2 @ wkvh, 1-term)      -> +v_b -> g_vt^T
// MODE 2: attno(fp16) @ wph (1-term) -> d_out fp32 (+proj_b)
// ============================================================
template<int MODE>
__global__ __launch_bounds__(256)
void gemm_kernel(const float* __restrict__ Af1, const float* __restrict__ Af2,
                 const __half* __restrict__ Ah1,
                 const __half* __restrict__ Wq, const __half* __restrict__ Wkvh,
                 const __half* __restrict__ Wkvl,
                 const float* __restrict__ bias1, const float* __restrict__ bias2,
                 const float* __restrict__ ls, float* __restrict__ outf)
{
    __shared__ __half Ah[2][128][40];
    __shared__ __half Bh[2][64][40];
    __shared__ __half Bl[(MODE == 3) ? 2 : 1][(MODE == 3) ? 64 : 8][40];

    const int tid = threadIdx.x, w = tid >> 5, lane = tid & 31;
    const int wm = w >> 1, wn = w & 1;
    const int row0 = blockIdx.y * 128;

    bool is_q = false;
    int col0;
    const float* Agf = nullptr;
    const __half *Whg, *Wlg = nullptr;
    if (MODE == 3) {
        is_q = (blockIdx.x < 3);
        col0 = (is_q ? blockIdx.x : blockIdx.x - 3) * 64;
        Agf = is_q ? Af1 : Af2;
        Whg = is_q ? Wq : Wkvh;
        Wlg = Wkvl;
    } else {
        col0 = blockIdx.x * 64;
        Whg = Wq;
    }
    // 2-term only for k columns (bx 3..5); v (bx 6..8) is 1-term
    const bool two = (MODE == 3) && !is_q && (blockIdx.x < 6);

    auto load_B = [&](int s, int buf) {
        const int k0 = s * 32;
        const int r = tid >> 2, c8 = (tid & 3) * 8;
        cpa16(&Bh[buf][r][c8], &Whg[(size_t)(col0 + r) * C_DIM + k0 + c8]);
        if (two)
            cpa16(&Bl[buf][r][c8], &Wlg[(size_t)(col0 + r) * C_DIM + k0 + c8]);
    };

    float4 areg[4];
    auto load_A_regs = [&](int s) {
        const int k0 = s * 32;
#pragma unroll
        for (int j = 0; j < 4; j++) {
            const int idx = j * 256 + tid;
            const int r = idx >> 3, f4 = (idx & 7) * 4;
            areg[j] = *(const float4*)&Agf[(size_t)(row0 + r) * C_DIM + k0 + f4];
        }
    };
    auto sts_A = [&](int buf) {
#pragma unroll
        for (int j = 0; j < 4; j++) {
            const int idx = j * 256 + tid;
            const int r = idx >> 3, f4 = (idx & 7) * 4;
            *(__half2*)&Ah[buf][r][f4]     = __floats2half2_rn(areg[j].x, areg[j].y);
            *(__half2*)&Ah[buf][r][f4 + 2] = __floats2half2_rn(areg[j].z, areg[j].w);
        }
    };
    auto load_A_cpa = [&](int s, int buf) {   // MODE 2: fp16 A via cp.async
        const int k0 = s * 32;
#pragma unroll
        for (int j = 0; j < 2; j++) {
            const int idx = j * 256 + tid;
            const int r = idx >> 2, c8 = (idx & 3) * 8;
            cpa16(&Ah[buf][r][c8], &Ah1[(size_t)(row0 + r) * C_DIM + k0 + c8]);
        }
    };

    float acc[2][4][4] = {};

    // ---- prologue ----
    if (MODE == 3) {
        load_A_regs(0);
        load_B(0, 0); cpa_commit();
        sts_A(0);
    } else {
        load_A_cpa(0, 0);
        load_B(0, 0); cpa_commit();
    }

    for (int s = 0; s < 6; s++) {
        const int buf = s & 1;
        if (s < 5) {
            if (MODE == 3) load_A_regs(s + 1);
            else           load_A_cpa(s + 1, buf ^ 1);
            load_B(s + 1, buf ^ 1); cpa_commit(); cpa_wait1();
        } else {
            cpa_wait0();
        }
        __syncthreads();

#pragma unroll
        for (int kf = 0; kf < 2; kf++) {
            unsigned ah[2][4];
#pragma unroll
            for (int mf = 0; mf < 2; mf++) {
                unsigned a = smem_u32(&Ah[buf][wm * 32 + mf * 16 + (lane & 15)][kf * 16 + (lane >> 4) * 8]);
                ldsm4(ah[mf][0], ah[mf][1], ah[mf][2], ah[mf][3], a);
            }
            unsigned bh_[4][2], bl_[4][2];
#pragma unroll
            for (int nt2 = 0; nt2 < 2; nt2++) {
                const int rowb = wn * 32 + nt2 * 16 + ((lane >> 4) << 3) + (lane & 7);
                const int colb = kf * 16 + ((lane >> 3) & 1) * 8;
                unsigned r0, r1, r2, r3;
                ldsm4(r0, r1, r2, r3, smem_u32(&Bh[buf][rowb][colb]));
                bh_[nt2 * 2][0] = r0; bh_[nt2 * 2][1] = r1;
                bh_[nt2 * 2 + 1][0] = r2; bh_[nt2 * 2 + 1][1] = r3;
                if (two) {
                    ldsm4(r0, r1, r2, r3, smem_u32(&Bl[buf & ((MODE == 3) ? 1 : 0)][rowb][colb]));
                    bl_[nt2 * 2][0] = r0; bl_[nt2 * 2][1] = r1;
                    bl_[nt2 * 2 + 1][0] = r2; bl_[nt2 * 2 + 1][1] = r3;
                }
            }
#pragma unroll
            for (int mf = 0; mf < 2; mf++)
#pragma unroll
                for (int nt = 0; nt < 4; nt++) {
                    mma16816(acc[mf][nt], ah[mf][0], ah[mf][1], ah[mf][2], ah[mf][3], bh_[nt][0], bh_[nt][1]);
                    if (two)
                        mma16816(acc[mf][nt], ah[mf][0], ah[mf][1], ah[mf][2], ah[mf][3], bl_[nt][0], bl_[nt][1]);
                }
        }

        if (MODE == 3 && s < 5) sts_A(buf ^ 1);   // LDG data arrived during compute
        __syncthreads();
    }

    // ---- epilogue ----
    if (MODE == 2) {
#pragma unroll
        for (int mf = 0; mf < 2; mf++) {
            const int rlo = row0 + wm * 32 + mf * 16 + (lane >> 2);
#pragma unroll
            for (int nt = 0; nt < 4; nt++) {
                const int cc = col0 + wn * 32 + nt * 8 + (lane & 3) * 2;
#pragma unroll
                for (int half_ = 0; half_ < 2; half_++) {
                    const int r = rlo + half_ * 8;
                    float2 o = make_float2(acc[mf][nt][half_ * 2 + 0] + bias1[cc],
                                           acc[mf][nt][half_ * 2 + 1] + bias1[cc + 1]);
                    *(float2*)&outf[(size_t)r * C_DIM + cc] = o;
                }
            }
        }
        return;
    }

    const int cbase = col0 + wn * 32;           // 32-aligned
    const bool is_v = !is_q && (cbase >= C_DIM);

    if (is_v) {
        // v columns: add v_b, write transposed [d][n] fp16
#pragma unroll
        for (int mf = 0; mf < 2; mf++) {
            const int rlo = row0 + wm * 32 + mf * 16 + (lane >> 2);
#pragma unroll
            for (int nt = 0; nt < 4; nt++) {
                const int cv = cbase - C_DIM + nt * 8 + (lane & 3) * 2;
                const int h = cv >> 5, d = cv & 31;
#pragma unroll
                for (int half_ = 0; half_ < 2; half_++) {
                    const int r = rlo + half_ * 8;
                    const int b = r >> 9, n = r & 511;
                    const float v0 = acc[mf][nt][half_ * 2 + 0] + bias2[cv];
                    const float v1 = acc[mf][nt][half_ * 2 + 1] + bias2[cv + 1];
                    g_vt[((size_t)(b * HEADS + h) * HD + d) * SEQ + n]     = __float2half_rn(v0);
                    g_vt[((size_t)(b * HEADS + h) * HD + d + 1) * SEQ + n] = __float2half_rn(v1);
                }
            }
        }
        return;
    }

    // q or k columns: fused L2-normalize (+ scale*log2e for q)
    const int h = cbase >> 5;
    float hsc = 1.0f;
    if (is_q) hsc = __expf(fminf(ls[h], LOGIT_MAX)) * LOG2E;

#pragma unroll
    for (int mf = 0; mf < 2; mf++) {
        const int rlo = row0 + wm * 32 + mf * 16 + (lane >> 2);
        float va[4][4];
        float ss0 = 0.f, ss1 = 0.f;
#pragma unroll
        for (int nt = 0; nt < 4; nt++) {
            const int cc = cbase + nt * 8 + (lane & 3) * 2;
            float b0 = 0.f, b1 = 0.f;
            if (is_q) { b0 = bias1[cc]; b1 = bias1[cc + 1]; }
            va[nt][0] = acc[mf][nt][0] + b0;
            va[nt][1] = acc[mf][nt][1] + b1;
            va[nt][2] = acc[mf][nt][2] + b0;
            va[nt][3] = acc[mf][nt][3] + b1;
            ss0 += va[nt][0] * va[nt][0] + va[nt][1] * va[nt][1];
            ss1 += va[nt][2] * va[nt][2] + va[nt][3] * va[nt][3];
        }
        ss0 += __shfl_xor_sync(0xffffffffu, ss0, 1);
        ss0 += __shfl_xor_sync(0xffffffffu, ss0, 2);
        ss1 += __shfl_xor_sync(0xffffffffu, ss1, 1);
        ss1 += __shfl_xor_sync(0xffffffffu, ss1, 2);
        const float inv0 = hsc / fmaxf(sqrtf(ss0), 1e-12f);
        const float inv1 = hsc / fmaxf(sqrtf(ss1), 1e-12f);

#pragma unroll
        for (int half_ = 0; half_ < 2; half_++) {
            const int r = rlo + half_ * 8;
            const int b = r >> 9, n = r & 511;
            const float inv = half_ ? inv1 : inv0;
            const size_t base = (((size_t)(b * HEADS + h) << 9) | n) * HD;
#pragma unroll
            for (int nt = 0; nt < 4; nt++) {
                const int d = nt * 8 + (lane & 3) * 2;
                const float v0 = va[nt][half_ * 2 + 0] * inv;
                const float v1 = va[nt][half_ * 2 + 1] * inv;
                __half* dst = is_q ? g_qh : g_kh;
                *(__half2*)&dst[base + d] = __floats2half2_rn(v0, v1);
            }
        }
    }
}

// ============================================================
// Attention per (b,h). 256 thr, 8 warps, 3 CTA/SM. (R9-proven)
// ============================================================
__device__ __forceinline__ unsigned kswz(int r, int cbytes) {
    return r * 64 + (cbytes ^ ((r & 6) * 8));
}

__global__ __launch_bounds__(256, 3)
void attn_kernel(const float* __restrict__ ls)
{
    extern __shared__ __half sm[];
    __half* Khs = sm;                    // 512 rows x 64B, swizzled
    __half* Vts = sm + 512 * 32;         // [32][520]

    const int bh = blockIdx.x;
    const int b = bh / HEADS, h = bh % HEADS;
    const int tid = threadIdx.x, w = tid >> 5, lane = tid & 31;

    const float bias2 = __expf(fminf(ls[h], LOGIT_MAX)) * LOG2E;

    const __half* kh = g_kh + (size_t)bh * SEQ * HD;
    const __half* vt = g_vt + (size_t)bh * HD * SEQ;

#pragma unroll
    for (int p = 0; p < 8; p++) {
        const int idx = p * 256 + tid;
        const int r = idx >> 2, cb = (idx & 3) * 16;
        *(uint4*)((char*)Khs + kswz(r, cb)) = *(const uint4*)&kh[r * HD + cb / 2];
    }
#pragma unroll
    for (int p = 0; p < 8; p++) {
        const int idx = p * 256 + tid;
        const int d = idx >> 6, c8 = (idx & 63) * 8;
        *(uint4*)&Vts[d * 520 + c8] = *(const uint4*)&vt[d * SEQ + c8];
    }
    __syncthreads();

    const __half* qh = g_qh + (size_t)bh * SEQ * HD;

    for (int mf = 0; mf < 4; mf++) {
        const int m0 = w * 64 + mf * 16;
        const int rlo = m0 + (lane >> 2);

        unsigned qhf[2][4];
#pragma unroll
        for (int kf = 0; kf < 2; kf++) {
            const int kb = kf * 16 + (lane & 3) * 2;
            qhf[kf][0] = *(const unsigned*)&qh[(size_t)rlo * HD + kb];
            qhf[kf][1] = *(const unsigned*)&qh[(size_t)(rlo + 8) * HD + kb];
            qhf[kf][2] = *(const unsigned*)&qh[(size_t)rlo * HD + kb + 8];
            qhf[kf][3] = *(const unsigned*)&qh[(size_t)(rlo + 8) * HD + kb + 8];
        }

        float O[4][4] = {};
        float l_lo = 0.f, l_hi = 0.f;

        for (int kc = 0; kc < 8; kc++) {
            float S[8][4] = {};
#pragma unroll
            for (int nt2 = 0; nt2 < 4; nt2++) {
                const int rowb = kc * 64 + nt2 * 16 + ((lane >> 4) << 3) + (lane & 7);
                const int colb2 = ((lane >> 3) & 1) * 16;
#pragma unroll
                for (int kf = 0; kf < 2; kf++) {
                    const unsigned off = kswz(rowb, kf * 32 + colb2);
                    unsigned kh0, kh1, kh2, kh3;
                    ldsm4(kh0, kh1, kh2, kh3, smem_u32((char*)Khs + off));
                    mma16816(S[nt2 * 2],     qhf[kf][0], qhf[kf][1], qhf[kf][2], qhf[kf][3], kh0, kh1);
                    mma16816(S[nt2 * 2 + 1], qhf[kf][0], qhf[kf][1], qhf[kf][2], qhf[kf][3], kh2, kh3);
                }
            }

#pragma unroll
            for (int nt = 0; nt < 8; nt++) {
                S[nt][0] = ex2(S[nt][0] - bias2);
                S[nt][1] = ex2(S[nt][1] - bias2);
                S[nt][2] = ex2(S[nt][2] - bias2);
                S[nt][3] = ex2(S[nt][3] - bias2);
                l_lo += S[nt][0] + S[nt][1];
                l_hi += S[nt][2] + S[nt][3];
            }

#pragma unroll
            for (int ks = 0; ks < 4; ks++) {
                const unsigned p0 = pack_h2(S[2 * ks][0], S[2 * ks][1]);
                const unsigned p1 = pack_h2(S[2 * ks][2], S[2 * ks][3]);
                const unsigned p2 = pack_h2(S[2 * ks + 1][0], S[2 * ks + 1][1]);
                const unsigned p3 = pack_h2(S[2 * ks + 1][2], S[2 * ks + 1][3]);
#pragma unroll
                for (int dt2 = 0; dt2 < 2; dt2++) {
                    const int rowd = dt2 * 16 + ((lane >> 4) << 3) + (lane & 7);
                    const int colk = kc * 64 + ks * 16 + ((lane >> 3) & 1) * 8;
                    unsigned v0, v1, v2, v3;
                    ldsm4(v0, v1, v2, v3, smem_u32(&Vts[rowd * 520 + colk]));
                    mma16816(O[dt2 * 2],     p0, p1, p2, p3, v0, v1);
                    mma16816(O[dt2 * 2 + 1], p0, p1, p2, p3, v2, v3);
                }
            }
        }

        l_lo += __shfl_xor_sync(0xffffffffu, l_lo, 1);
        l_lo += __shfl_xor_sync(0xffffffffu, l_lo, 2);
        l_hi += __shfl_xor_sync(0xffffffffu, l_hi, 1);
        l_hi += __shfl_xor_sync(0xffffffffu, l_hi, 2);
        const float il_lo = 1.0f / l_lo, il_hi = 1.0f / l_hi;
#pragma unroll
        for (int dt = 0; dt < 4; dt++) {
            __half2 o_lo = __floats2half2_rn(O[dt][0] * il_lo, O[dt][1] * il_lo);
            __half2 o_hi = __floats2half2_rn(O[dt][2] * il_hi, O[dt][3] * il_hi);
            const size_t base = ((size_t)b * SEQ + rlo) * C_DIM + h * HD + dt * 8 + (lane & 3) * 2;
            *(__half2*)&g_attno[base] = o_lo;
            *(__half2*)&g_attno[base + (size_t)8 * C_DIM] = o_hi;
        }
    }
}

// ============================================================
// Launch
// ============================================================
extern "C" void kernel_launch(void* const* d_in, const int* in_sizes, int n_in,
                              void* d_out, int out_size)
{
    (void)in_sizes; (void)n_in; (void)out_size;
    const float* x1     = (const float*)d_in[0];
    const float* x2     = (const float*)d_in[1];
    const float* q_w    = (const float*)d_in[2];
    const float* q_b    = (const float*)d_in[3];
    const float* kv_w   = (const float*)d_in[4];
    const float* v_b    = (const float*)d_in[5];
    const float* ls     = (const float*)d_in[6];
    const float* proj_w = (const float*)d_in[7];
    const float* proj_b = (const float*)d_in[8];
    float* out = (float*)d_out;

    __half *wqh, *wkvh, *wkvl, *wph, *attno;
    cudaGetSymbolAddress((void**)&wqh,  g_wqh);
    cudaGetSymbolAddress((void**)&wkvh, g_wkvh);
    cudaGetSymbolAddress((void**)&wkvl, g_wkvl);
    cudaGetSymbolAddress((void**)&wph,  g_wph);
    cudaGetSymbolAddress((void**)&attno, g_attno);

    wprep_kernel<<<72, 256>>>(q_w, kv_w, proj_w);

    // fused q + kv projections; A consumed fp32-direct (in-register convert)
    gemm_kernel<3><<<dim3(9, MROWS / 128), 256>>>(x1, x2, nullptr,
                                                  wqh, wkvh, wkvl,
                                                  q_b, v_b, ls, nullptr);

    const int smem_bytes = (512 * 32 + 32 * 520) * (int)sizeof(__half); // 66048
    cudaFuncSetAttribute(attn_kernel, cudaFuncAttributeMaxDynamicSharedMemorySize, smem_bytes);
    attn_kernel<<<BH, 256, smem_bytes>>>(ls);

    // output projection (1-term, fp16 A)
    gemm_kernel<2><<<dim3(3, MROWS / 128), 256>>>(nullptr, nullptr, attno,
                                                  wph, nullptr, nullptr,
                                                  proj_b, nullptr, nullptr, out);
}

// round 14
// speedup vs baseline: 1.5306x; 1.5306x over previous
#include <cuda_runtime.h>
#include <cuda_fp16.h>

#define C_DIM 192
#define HEADS 6
#define HD 32
#define BATCH 128
#define SEQ 512
#define MROWS (BATCH * SEQ)        // 65536
#define BH (BATCH * HEADS)         // 768
#define LOGIT_MAX 4.6051701859880914f
#define LOG2E 1.4426950408889634f

// ---------------- device-global scratch ----------------
__device__ __half g_qh[(size_t)BH * SEQ * HD];    // normalized * scale * log2e q
__device__ __half g_kh[(size_t)BH * SEQ * HD];    // normalized k
__device__ __half g_vt[(size_t)BH * HD * SEQ];    // v transposed per (b,h): [d][n]
__device__ __half g_attno[(size_t)MROWS * C_DIM];
__device__ __half g_x1h[(size_t)MROWS * C_DIM];
__device__ __half g_x2h[(size_t)MROWS * C_DIM];
__device__ __half g_wqh[C_DIM * C_DIM];
__device__ __half g_wkvh[2 * C_DIM * C_DIM];
__device__ __half g_wkvl[2 * C_DIM * C_DIM];
__device__ __half g_wph[C_DIM * C_DIM];

// ---------------- helpers ----------------
__device__ __forceinline__ unsigned smem_u32(const void* p) {
    return (unsigned)__cvta_generic_to_shared(p);
}
__device__ __forceinline__ void ldsm4(unsigned& r0, unsigned& r1, unsigned& r2, unsigned& r3, unsigned a) {
    asm volatile("ldmatrix.sync.aligned.m8n8.x4.shared.b16 {%0,%1,%2,%3},[%4];\n"
                 : "=r"(r0), "=r"(r1), "=r"(r2), "=r"(r3) : "r"(a));
}
__device__ __forceinline__ void mma16816(float* c, unsigned a0, unsigned a1, unsigned a2, unsigned a3,
                                         unsigned b0, unsigned b1) {
    asm volatile("mma.sync.aligned.m16n8k16.row.col.f32.f16.f16.f32 "
                 "{%0,%1,%2,%3},{%4,%5,%6,%7},{%8,%9},{%0,%1,%2,%3};\n"
                 : "+f"(c[0]), "+f"(c[1]), "+f"(c[2]), "+f"(c[3])
                 : "r"(a0), "r"(a1), "r"(a2), "r"(a3), "r"(b0), "r"(b1));
}
__device__ __forceinline__ void split2(float x, float y, __half2& hi, __half2& lo) {
    __half hx = __float2half_rn(x), hy = __float2half_rn(y);
    hi = __halves2half2(hx, hy);
    lo = __floats2half2_rn(x - __half2float(hx), y - __half2float(hy));
}
__device__ __forceinline__ unsigned pack_h2(float a, float b) {
    __half2 t = __floats2half2_rn(a, b);
    return *(unsigned*)&t;
}
__device__ __forceinline__ float ex2(float x) {
    float y;
    asm("ex2.approx.ftz.f32 %0, %1;" : "=f"(y) : "f"(x));
    return y;
}
__device__ __forceinline__ void cpa16(void* s, const void* g) {
    asm volatile("cp.async.ca.shared.global [%0], [%1], 16;\n" :: "r"(smem_u32(s)), "l"(g));
}
__device__ __forceinline__ void cpa_commit() { asm volatile("cp.async.commit_group;\n"); }
__device__ __forceinline__ void cpa_wait1()  { asm volatile("cp.async.wait_group 1;\n"); }
__device__ __forceinline__ void cpa_wait0()  { asm volatile("cp.async.wait_group 0;\n"); }

// ============================================================
// x1+x2 fp32 -> fp16. 6144 blocks per tensor.
// ============================================================
__global__ __launch_bounds__(256)
void tohalf2_kernel(const float* __restrict__ x1, const float* __restrict__ x2)
{
    int blk = blockIdx.x;
    const float* src;  __half* dst;
    if (blk < 6144) { src = x1; dst = g_x1h; }
    else            { src = x2; dst = g_x2h; blk -= 6144; }
    const int i = blk * 256 + threadIdx.x;
    const float4 a = *(const float4*)&src[(size_t)i * 8];
    const float4 b = *(const float4*)&src[(size_t)i * 8 + 4];
    __half2 h[4];
    h[0] = __floats2half2_rn(a.x, a.y);
    h[1] = __floats2half2_rn(a.z, a.w);
    h[2] = __floats2half2_rn(b.x, b.y);
    h[3] = __floats2half2_rn(b.z, b.w);
    *(uint4*)&dst[(size_t)i * 8] = *(uint4*)h;
}

// ============================================================
// Weight prep: q_w -> hi; kv_w -> hi+lo split; proj_w -> hi.
// blocks: [0,18) q_w, [18,54) kv_w, [54,72) proj_w.
// ============================================================
__global__ __launch_bounds__(256)
void wprep_kernel(const float* __restrict__ qw, const float* __restrict__ kvw,
                  const float* __restrict__ pw)
{
    int blk = blockIdx.x;
    if (blk >= 18 && blk < 54) {            // kv: split
        const int i = (blk - 18) * 256 + threadIdx.x;
        const float4 a = *(const float4*)&kvw[(size_t)i * 8];
        const float4 b = *(const float4*)&kvw[(size_t)i * 8 + 4];
        __half2 h[4], l[4];
        split2(a.x, a.y, h[0], l[0]);
        split2(a.z, a.w, h[1], l[1]);
        split2(b.x, b.y, h[2], l[2]);
        split2(b.z, b.w, h[3], l[3]);
        *(uint4*)&g_wkvh[(size_t)i * 8] = *(uint4*)h;
        *(uint4*)&g_wkvl[(size_t)i * 8] = *(uint4*)l;
    } else {                                 // q / proj: plain fp16
        const float* src;  __half* dst;
        if (blk < 18) { src = qw; dst = g_wqh; }
        else          { src = pw; dst = g_wph; blk -= 54; }
        const int i = blk * 256 + threadIdx.x;
        const float4 a = *(const float4*)&src[(size_t)i * 8];
        const float4 b = *(const float4*)&src[(size_t)i * 8 + 4];
        __half2 h[4];
        h[0] = __floats2half2_rn(a.x, a.y);
        h[1] = __floats2half2_rn(a.z, a.w);
        h[2] = __floats2half2_rn(b.x, b.y);
        h[3] = __floats2half2_rn(b.z, b.w);
        *(uint4*)&dst[(size_t)i * 8] = *(uint4*)h;
    }
}

// ============================================================
// Tensor-core GEMM (R12-proven body). BM=128, BN=64, BK=32, 8 warps.
// MODE 3: fused q+kv (A = pre-converted fp16):
//   bx<3:   q (x1h @ wqh, 1-term) -> +q_b, L2-norm, *exp(ls)*log2e -> g_qh
//   bx 3-5: k (x2h @ wkvh+wkvl, 2-term) -> L2-norm -> g_kh
//   bx 6-8: v (x2h @ wkvh, 1-term)      -> +v_b -> g_vt^T
// MODE 2: attno @ wph (1-term) -> d_out fp32 (+proj_b)
// ============================================================
template<int MODE>
__global__ __launch_bounds__(256)
void gemm_kernel(const __half* __restrict__ A1, const __half* __restrict__ A2,
                 const __half* __restrict__ Wq, const __half* __restrict__ Wkvh,
                 const __half* __restrict__ Wkvl,
                 const float* __restrict__ bias1, const float* __restrict__ bias2,
                 const float* __restrict__ ls, float* __restrict__ outf)
{
    __shared__ __half Ah[2][128][40];
    __shared__ __half Bh[2][64][40];
    __shared__ __half Bl[(MODE == 3) ? 2 : 1][(MODE == 3) ? 64 : 8][40];

    const int tid = threadIdx.x, w = tid >> 5, lane = tid & 31;
    const int wm = w >> 1, wn = w & 1;
    const int row0 = blockIdx.y * 128;

    bool is_q = false;
    int col0;
    const __half *Ag, *Whg, *Wlg = nullptr;
    if (MODE == 3) {
        is_q = (blockIdx.x < 3);
        col0 = (is_q ? blockIdx.x : blockIdx.x - 3) * 64;
        Ag  = is_q ? A1 : A2;
        Whg = is_q ? Wq : Wkvh;
        Wlg = Wkvl;
    } else {
        col0 = blockIdx.x * 64;
        Ag = A1;  Whg = Wq;
    }
    // 2-term only for k columns (bx 3..5); q and v are 1-term
    const bool two = (MODE == 3) && !is_q && (blockIdx.x < 6);

    auto load_stage = [&](int s, int buf) {
        const int k0 = s * 32;
#pragma unroll
        for (int j = 0; j < 2; j++) {
            const int idx = j * 256 + tid;
            const int r = idx >> 2, c8 = (idx & 3) * 8;
            cpa16(&Ah[buf][r][c8], &Ag[(size_t)(row0 + r) * C_DIM + k0 + c8]);
        }
        {
            const int r = tid >> 2, c8 = (tid & 3) * 8;
            cpa16(&Bh[buf][r][c8], &Whg[(size_t)(col0 + r) * C_DIM + k0 + c8]);
            if (two)
                cpa16(&Bl[buf][r][c8], &Wlg[(size_t)(col0 + r) * C_DIM + k0 + c8]);
        }
    };

    float acc[2][4][4] = {};

    load_stage(0, 0);
    cpa_commit();

    for (int s = 0; s < 6; s++) {
        const int buf = s & 1;
        if (s < 5) { load_stage(s + 1, buf ^ 1); cpa_commit(); cpa_wait1(); }
        else       { cpa_wait0(); }
        __syncthreads();

#pragma unroll
        for (int kf = 0; kf < 2; kf++) {
            unsigned ah[2][4];
#pragma unroll
            for (int mf = 0; mf < 2; mf++) {
                unsigned a = smem_u32(&Ah[buf][wm * 32 + mf * 16 + (lane & 15)][kf * 16 + (lane >> 4) * 8]);
                ldsm4(ah[mf][0], ah[mf][1], ah[mf][2], ah[mf][3], a);
            }
            unsigned bh_[4][2], bl_[4][2];
#pragma unroll
            for (int nt2 = 0; nt2 < 2; nt2++) {
                const int rowb = wn * 32 + nt2 * 16 + ((lane >> 4) << 3) + (lane & 7);
                const int colb = kf * 16 + ((lane >> 3) & 1) * 8;
                unsigned r0, r1, r2, r3;
                ldsm4(r0, r1, r2, r3, smem_u32(&Bh[buf][rowb][colb]));
                bh_[nt2 * 2][0] = r0; bh_[nt2 * 2][1] = r1;
                bh_[nt2 * 2 + 1][0] = r2; bh_[nt2 * 2 + 1][1] = r3;
                if (two) {
                    ldsm4(r0, r1, r2, r3, smem_u32(&Bl[buf & ((MODE == 3) ? 1 : 0)][rowb][colb]));
                    bl_[nt2 * 2][0] = r0; bl_[nt2 * 2][1] = r1;
                    bl_[nt2 * 2 + 1][0] = r2; bl_[nt2 * 2 + 1][1] = r3;
                }
            }
#pragma unroll
            for (int mf = 0; mf < 2; mf++)
#pragma unroll
                for (int nt = 0; nt < 4; nt++) {
                    mma16816(acc[mf][nt], ah[mf][0], ah[mf][1], ah[mf][2], ah[mf][3], bh_[nt][0], bh_[nt][1]);
                    if (two)
                        mma16816(acc[mf][nt], ah[mf][0], ah[mf][1], ah[mf][2], ah[mf][3], bl_[nt][0], bl_[nt][1]);
                }
        }
        __syncthreads();
    }

    // ---- epilogue ----
    if (MODE == 2) {
#pragma unroll
        for (int mf = 0; mf < 2; mf++) {
            const int rlo = row0 + wm * 32 + mf * 16 + (lane >> 2);
#pragma unroll
            for (int nt = 0; nt < 4; nt++) {
                const int cc = col0 + wn * 32 + nt * 8 + (lane & 3) * 2;
#pragma unroll
                for (int half_ = 0; half_ < 2; half_++) {
                    const int r = rlo + half_ * 8;
                    float2 o = make_float2(acc[mf][nt][half_ * 2 + 0] + bias1[cc],
                                           acc[mf][nt][half_ * 2 + 1] + bias1[cc + 1]);
                    *(float2*)&outf[(size_t)r * C_DIM + cc] = o;
                }
            }
        }
        return;
    }

    const int cbase = col0 + wn * 32;           // 32-aligned
    const bool is_v = !is_q && (cbase >= C_DIM);

    if (is_v) {
        // v columns: add v_b, write transposed [d][n] fp16
#pragma unroll
        for (int mf = 0; mf < 2; mf++) {
            const int rlo = row0 + wm * 32 + mf * 16 + (lane >> 2);
#pragma unroll
            for (int nt = 0; nt < 4; nt++) {
                const int cv = cbase - C_DIM + nt * 8 + (lane & 3) * 2;
                const int h = cv >> 5, d = cv & 31;
#pragma unroll
                for (int half_ = 0; half_ < 2; half_++) {
                    const int r = rlo + half_ * 8;
                    const int b = r >> 9, n = r & 511;
                    const float v0 = acc[mf][nt][half_ * 2 + 0] + bias2[cv];
                    const float v1 = acc[mf][nt][half_ * 2 + 1] + bias2[cv + 1];
                    g_vt[((size_t)(b * HEADS + h) * HD + d) * SEQ + n]     = __float2half_rn(v0);
                    g_vt[((size_t)(b * HEADS + h) * HD + d + 1) * SEQ + n] = __float2half_rn(v1);
                }
            }
        }
        return;
    }

    // q or k columns: fused L2-normalize (+ scale*log2e for q)
    const int h = cbase >> 5;
    float hsc = 1.0f;
    if (is_q) hsc = __expf(fminf(ls[h], LOGIT_MAX)) * LOG2E;

#pragma unroll
    for (int mf = 0; mf < 2; mf++) {
        const int rlo = row0 + wm * 32 + mf * 16 + (lane >> 2);
        float va[4][4];
        float ss0 = 0.f, ss1 = 0.f;
#pragma unroll
        for (int nt = 0; nt < 4; nt++) {
            const int cc = cbase + nt * 8 + (lane & 3) * 2;
            float b0 = 0.f, b1 = 0.f;
            if (is_q) { b0 = bias1[cc]; b1 = bias1[cc + 1]; }
            va[nt][0] = acc[mf][nt][0] + b0;
            va[nt][1] = acc[mf][nt][1] + b1;
            va[nt][2] = acc[mf][nt][2] + b0;
            va[nt][3] = acc[mf][nt][3] + b1;
            ss0 += va[nt][0] * va[nt][0] + va[nt][1] * va[nt][1];
            ss1 += va[nt][2] * va[nt][2] + va[nt][3] * va[nt][3];
        }
        ss0 += __shfl_xor_sync(0xffffffffu, ss0, 1);
        ss0 += __shfl_xor_sync(0xffffffffu, ss0, 2);
        ss1 += __shfl_xor_sync(0xffffffffu, ss1, 1);
        ss1 += __shfl_xor_sync(0xffffffffu, ss1, 2);
        const float inv0 = hsc / fmaxf(sqrtf(ss0), 1e-12f);
        const float inv1 = hsc / fmaxf(sqrtf(ss1), 1e-12f);

#pragma unroll
        for (int half_ = 0; half_ < 2; half_++) {
            const int r = rlo + half_ * 8;
            const int b = r >> 9, n = r & 511;
            const float inv = half_ ? inv1 : inv0;
            const size_t base = (((size_t)(b * HEADS + h) << 9) | n) * HD;
#pragma unroll
            for (int nt = 0; nt < 4; nt++) {
                const int d = nt * 8 + (lane & 3) * 2;
                const float v0 = va[nt][half_ * 2 + 0] * inv;
                const float v1 = va[nt][half_ * 2 + 1] * inv;
                __half* dst = is_q ? g_qh : g_kh;
                *(__half2*)&dst[base + d] = __floats2half2_rn(v0, v1);
            }
        }
    }
}

// ============================================================
// Attention per (b,h). 256 thr, 8 warps, 3 CTA/SM. (R9-proven)
// ============================================================
__device__ __forceinline__ unsigned kswz(int r, int cbytes) {
    return r * 64 + (cbytes ^ ((r & 6) * 8));
}

__global__ __launch_bounds__(256, 3)
void attn_kernel(const float* __restrict__ ls)
{
    extern __shared__ __half sm[];
    __half* Khs = sm;                    // 512 rows x 64B, swizzled
    __half* Vts = sm + 512 * 32;         // [32][520]

    const int bh = blockIdx.x;
    const int b = bh / HEADS, h = bh % HEADS;
    const int tid = threadIdx.x, w = tid >> 5, lane = tid & 31;

    const float bias2 = __expf(fminf(ls[h], LOGIT_MAX)) * LOG2E;

    const __half* kh = g_kh + (size_t)bh * SEQ * HD;
    const __half* vt = g_vt + (size_t)bh * HD * SEQ;

#pragma unroll
    for (int p = 0; p < 8; p++) {
        const int idx = p * 256 + tid;
        const int r = idx >> 2, cb = (idx & 3) * 16;
        *(uint4*)((char*)Khs + kswz(r, cb)) = *(const uint4*)&kh[r * HD + cb / 2];
    }
#pragma unroll
    for (int p = 0; p < 8; p++) {
        const int idx = p * 256 + tid;
        const int d = idx >> 6, c8 = (idx & 63) * 8;
        *(uint4*)&Vts[d * 520 + c8] = *(const uint4*)&vt[d * SEQ + c8];
    }
    __syncthreads();

    const __half* qh = g_qh + (size_t)bh * SEQ * HD;

    for (int mf = 0; mf < 4; mf++) {
        const int m0 = w * 64 + mf * 16;
        const int rlo = m0 + (lane >> 2);

        unsigned qhf[2][4];
#pragma unroll
        for (int kf = 0; kf < 2; kf++) {
            const int kb = kf * 16 + (lane & 3) * 2;
            qhf[kf][0] = *(const unsigned*)&qh[(size_t)rlo * HD + kb];
            qhf[kf][1] = *(const unsigned*)&qh[(size_t)(rlo + 8) * HD + kb];
            qhf[kf][2] = *(const unsigned*)&qh[(size_t)rlo * HD + kb + 8];
            qhf[kf][3] = *(const unsigned*)&qh[(size_t)(rlo + 8) * HD + kb + 8];
        }

        float O[4][4] = {};
        float l_lo = 0.f, l_hi = 0.f;

        for (int kc = 0; kc < 8; kc++) {
            float S[8][4] = {};
#pragma unroll
            for (int nt2 = 0; nt2 < 4; nt2++) {
                const int rowb = kc * 64 + nt2 * 16 + ((lane >> 4) << 3) + (lane & 7);
                const int colb2 = ((lane >> 3) & 1) * 16;
#pragma unroll
                for (int kf = 0; kf < 2; kf++) {
                    const unsigned off = kswz(rowb, kf * 32 + colb2);
                    unsigned kh0, kh1, kh2, kh3;
                    ldsm4(kh0, kh1, kh2, kh3, smem_u32((char*)Khs + off));
                    mma16816(S[nt2 * 2],     qhf[kf][0], qhf[kf][1], qhf[kf][2], qhf[kf][3], kh0, kh1);
                    mma16816(S[nt2 * 2 + 1], qhf[kf][0], qhf[kf][1], qhf[kf][2], qhf[kf][3], kh2, kh3);
                }
            }

#pragma unroll
            for (int nt = 0; nt < 8; nt++) {
                S[nt][0] = ex2(S[nt][0] - bias2);
                S[nt][1] = ex2(S[nt][1] - bias2);
                S[nt][2] = ex2(S[nt][2] - bias2);
                S[nt][3] = ex2(S[nt][3] - bias2);
                l_lo += S[nt][0] + S[nt][1];
                l_hi += S[nt][2] + S[nt][3];
            }

#pragma unroll
            for (int ks = 0; ks < 4; ks++) {
                const unsigned p0 = pack_h2(S[2 * ks][0], S[2 * ks][1]);
                const unsigned p1 = pack_h2(S[2 * ks][2], S[2 * ks][3]);
                const unsigned p2 = pack_h2(S[2 * ks + 1][0], S[2 * ks + 1][1]);
                const unsigned p3 = pack_h2(S[2 * ks + 1][2], S[2 * ks + 1][3]);
#pragma unroll
                for (int dt2 = 0; dt2 < 2; dt2++) {
                    const int rowd = dt2 * 16 + ((lane >> 4) << 3) + (lane & 7);
                    const int colk = kc * 64 + ks * 16 + ((lane >> 3) & 1) * 8;
                    unsigned v0, v1, v2, v3;
                    ldsm4(v0, v1, v2, v3, smem_u32(&Vts[rowd * 520 + colk]));
                    mma16816(O[dt2 * 2],     p0, p1, p2, p3, v0, v1);
                    mma16816(O[dt2 * 2 + 1], p0, p1, p2, p3, v2, v3);
                }
            }
        }

        l_lo += __shfl_xor_sync(0xffffffffu, l_lo, 1);
        l_lo += __shfl_xor_sync(0xffffffffu, l_lo, 2);
        l_hi += __shfl_xor_sync(0xffffffffu, l_hi, 1);
        l_hi += __shfl_xor_sync(0xffffffffu, l_hi, 2);
        const float il_lo = 1.0f / l_lo, il_hi = 1.0f / l_hi;
#pragma unroll
        for (int dt = 0; dt < 4; dt++) {
            __half2 o_lo = __floats2half2_rn(O[dt][0] * il_lo, O[dt][1] * il_lo);
            __half2 o_hi = __floats2half2_rn(O[dt][2] * il_hi, O[dt][3] * il_hi);
            const size_t base = ((size_t)b * SEQ + rlo) * C_DIM + h * HD + dt * 8 + (lane & 3) * 2;
            *(__half2*)&g_attno[base] = o_lo;
            *(__half2*)&g_attno[base + (size_t)8 * C_DIM] = o_hi;
        }
    }
}

// ============================================================
// Launch
// ============================================================
extern "C" void kernel_launch(void* const* d_in, const int* in_sizes, int n_in,
                              void* d_out, int out_size)
{
    (void)in_sizes; (void)n_in; (void)out_size;
    const float* x1     = (const float*)d_in[0];
    const float* x2     = (const float*)d_in[1];
    const float* q_w    = (const float*)d_in[2];
    const float* q_b    = (const float*)d_in[3];
    const float* kv_w   = (const float*)d_in[4];
    const float* v_b    = (const float*)d_in[5];
    const float* ls     = (const float*)d_in[6];
    const float* proj_w = (const float*)d_in[7];
    const float* proj_b = (const float*)d_in[8];
    float* out = (float*)d_out;

    __half *x1h, *x2h, *wqh, *wkvh, *wkvl, *wph, *attno;
    cudaGetSymbolAddress((void**)&x1h,  g_x1h);
    cudaGetSymbolAddress((void**)&x2h,  g_x2h);
    cudaGetSymbolAddress((void**)&wqh,  g_wqh);
    cudaGetSymbolAddress((void**)&wkvh, g_wkvh);
    cudaGetSymbolAddress((void**)&wkvl, g_wkvl);
    cudaGetSymbolAddress((void**)&wph,  g_wph);
    cudaGetSymbolAddress((void**)&attno, g_attno);

    tohalf2_kernel<<<12288, 256>>>(x1, x2);
    wprep_kernel<<<72, 256>>>(q_w, kv_w, proj_w);

    // fused q + kv projections (q: 1-term, k: 2-term, v: 1-term)
    gemm_kernel<3><<<dim3(9, MROWS / 128), 256>>>(x1h, x2h, wqh, wkvh, wkvl,
                                                  q_b, v_b, ls, nullptr);

    const int smem_bytes = (512 * 32 + 32 * 520) * (int)sizeof(__half); // 66048
    cudaFuncSetAttribute(attn_kernel, cudaFuncAttributeMaxDynamicSharedMemorySize, smem_bytes);
    attn_kernel<<<BH, 256, smem_bytes>>>(ls);

    // output projection (1-term)
    gemm_kernel<2><<<dim3(3, MROWS / 128), 256>>>(attno, nullptr, wph, nullptr, nullptr,
                                                  proj_b, nullptr, nullptr, out);
}

// round 15
// speedup vs baseline: 1.5549x; 1.0159x over previous
#include <cuda_runtime.h>
#include <cuda_fp16.h>

#define C_DIM 192
#define HEADS 6
#define HD 32
#define BATCH 128
#define SEQ 512
#define MROWS (BATCH * SEQ)        // 65536
#define BH (BATCH * HEADS)         // 768
#define LOGIT_MAX 4.6051701859880914f
#define LOG2E 1.4426950408889634f

// ---------------- device-global scratch ----------------
__device__ __half g_qh[(size_t)BH * SEQ * HD];    // normalized * scale * log2e q
__device__ __half g_kh[(size_t)BH * SEQ * HD];    // normalized k
__device__ __half g_vt[(size_t)BH * HD * SEQ];    // v transposed per (b,h): [d][n]
__device__ __half g_attno[(size_t)MROWS * C_DIM];
__device__ __half g_x1h[(size_t)MROWS * C_DIM];
__device__ __half g_x2h[(size_t)MROWS * C_DIM];
__device__ __half g_wqh[C_DIM * C_DIM];
__device__ __half g_wkvh[2 * C_DIM * C_DIM];
__device__ __half g_wkvl[2 * C_DIM * C_DIM];
__device__ __half g_wph[C_DIM * C_DIM];

// ---------------- helpers ----------------
__device__ __forceinline__ unsigned smem_u32(const void* p) {
    return (unsigned)__cvta_generic_to_shared(p);
}
__device__ __forceinline__ void ldsm4(unsigned& r0, unsigned& r1, unsigned& r2, unsigned& r3, unsigned a) {
    asm volatile("ldmatrix.sync.aligned.m8n8.x4.shared.b16 {%0,%1,%2,%3},[%4];\n"
                 : "=r"(r0), "=r"(r1), "=r"(r2), "=r"(r3) : "r"(a));
}
__device__ __forceinline__ void mma16816(float* c, unsigned a0, unsigned a1, unsigned a2, unsigned a3,
                                         unsigned b0, unsigned b1) {
    asm volatile("mma.sync.aligned.m16n8k16.row.col.f32.f16.f16.f32 "
                 "{%0,%1,%2,%3},{%4,%5,%6,%7},{%8,%9},{%0,%1,%2,%3};\n"
                 : "+f"(c[0]), "+f"(c[1]), "+f"(c[2]), "+f"(c[3])
                 : "r"(a0), "r"(a1), "r"(a2), "r"(a3), "r"(b0), "r"(b1));
}
__device__ __forceinline__ void split2(float x, float y, __half2& hi, __half2& lo) {
    __half hx = __float2half_rn(x), hy = __float2half_rn(y);
    hi = __halves2half2(hx, hy);
    lo = __floats2half2_rn(x - __half2float(hx), y - __half2float(hy));
}
__device__ __forceinline__ unsigned pack_h2(float a, float b) {
    __half2 t = __floats2half2_rn(a, b);
    return *(unsigned*)&t;
}
__device__ __forceinline__ float ex2(float x) {
    float y;
    asm("ex2.approx.ftz.f32 %0, %1;" : "=f"(y) : "f"(x));
    return y;
}
__device__ __forceinline__ void cpa16(void* s, const void* g) {
    asm volatile("cp.async.ca.shared.global [%0], [%1], 16;\n" :: "r"(smem_u32(s)), "l"(g));
}
__device__ __forceinline__ void cpa_commit() { asm volatile("cp.async.commit_group;\n"); }
__device__ __forceinline__ void cpa_wait2()  { asm volatile("cp.async.wait_group 2;\n"); }
__device__ __forceinline__ void cpa_wait1()  { asm volatile("cp.async.wait_group 1;\n"); }
__device__ __forceinline__ void cpa_wait0()  { asm volatile("cp.async.wait_group 0;\n"); }

// ============================================================
// Combined prep: x1/x2 fp32->fp16 (blocks < 12288) and
// weight prep (blocks 12288..12359: q hi, kv split, proj hi).
// ============================================================
__global__ __launch_bounds__(256)
void prep_kernel(const float* __restrict__ x1, const float* __restrict__ x2,
                 const float* __restrict__ qw, const float* __restrict__ kvw,
                 const float* __restrict__ pw)
{
    int blk = blockIdx.x;
    if (blk < 12288) {
        const float* src;  __half* dst;
        if (blk < 6144) { src = x1; dst = g_x1h; }
        else            { src = x2; dst = g_x2h; blk -= 6144; }
        const int i = blk * 256 + threadIdx.x;
        const float4 a = *(const float4*)&src[(size_t)i * 8];
        const float4 b = *(const float4*)&src[(size_t)i * 8 + 4];
        __half2 h[4];
        h[0] = __floats2half2_rn(a.x, a.y);
        h[1] = __floats2half2_rn(a.z, a.w);
        h[2] = __floats2half2_rn(b.x, b.y);
        h[3] = __floats2half2_rn(b.z, b.w);
        *(uint4*)&dst[(size_t)i * 8] = *(uint4*)h;
        return;
    }
    blk -= 12288;
    if (blk >= 18 && blk < 54) {            // kv: split
        const int i = (blk - 18) * 256 + threadIdx.x;
        const float4 a = *(const float4*)&kvw[(size_t)i * 8];
        const float4 b = *(const float4*)&kvw[(size_t)i * 8 + 4];
        __half2 h[4], l[4];
        split2(a.x, a.y, h[0], l[0]);
        split2(a.z, a.w, h[1], l[1]);
        split2(b.x, b.y, h[2], l[2]);
        split2(b.z, b.w, h[3], l[3]);
        *(uint4*)&g_wkvh[(size_t)i * 8] = *(uint4*)h;
        *(uint4*)&g_wkvl[(size_t)i * 8] = *(uint4*)l;
    } else {                                 // q / proj: plain fp16
        const float* src;  __half* dst;
        if (blk < 18) { src = qw; dst = g_wqh; }
        else          { src = pw; dst = g_wph; blk -= 54; }
        const int i = blk * 256 + threadIdx.x;
        const float4 a = *(const float4*)&src[(size_t)i * 8];
        const float4 b = *(const float4*)&src[(size_t)i * 8 + 4];
        __half2 h[4];
        h[0] = __floats2half2_rn(a.x, a.y);
        h[1] = __floats2half2_rn(a.z, a.w);
        h[2] = __floats2half2_rn(b.x, b.y);
        h[3] = __floats2half2_rn(b.z, b.w);
        *(uint4*)&dst[(size_t)i * 8] = *(uint4*)h;
    }
}

// ============================================================
// Tensor-core GEMM. BM=128, BN=64, BK=32, 8 warps.
// MODE 3: fused q+kv (2-stage pipeline, proven):
//   bx<3:   q (x1h @ wqh, 1-term) -> +q_b, L2-norm, *exp(ls)*log2e -> g_qh
//   bx 3-5: k (x2h @ wkvh+wkvl, 2-term) -> L2-norm -> g_kh
//   bx 6-8: v (x2h @ wkvh, 1-term)      -> +v_b -> g_vt^T
// MODE 2: attno @ wph (1-term), 3-stage pipeline (latency-bound fix)
//         -> d_out fp32 (+proj_b)
// ============================================================
template<int MODE>
__global__ __launch_bounds__(256)
void gemm_kernel(const __half* __restrict__ A1, const __half* __restrict__ A2,
                 const __half* __restrict__ Wq, const __half* __restrict__ Wkvh,
                 const __half* __restrict__ Wkvl,
                 const float* __restrict__ bias1, const float* __restrict__ bias2,
                 const float* __restrict__ ls, float* __restrict__ outf)
{
    constexpr int ST = (MODE == 2) ? 3 : 2;
    __shared__ __half Ah[ST][128][40];
    __shared__ __half Bh[ST][64][40];
    __shared__ __half Bl[(MODE == 3) ? 2 : 1][(MODE == 3) ? 64 : 8][40];

    const int tid = threadIdx.x, w = tid >> 5, lane = tid & 31;
    const int wm = w >> 1, wn = w & 1;
    const int row0 = blockIdx.y * 128;

    bool is_q = false;
    int col0;
    const __half *Ag, *Whg, *Wlg = nullptr;
    if (MODE == 3) {
        is_q = (blockIdx.x < 3);
        col0 = (is_q ? blockIdx.x : blockIdx.x - 3) * 64;
        Ag  = is_q ? A1 : A2;
        Whg = is_q ? Wq : Wkvh;
        Wlg = Wkvl;
    } else {
        col0 = blockIdx.x * 64;
        Ag = A1;  Whg = Wq;
    }
    // 2-term only for k columns (bx 3..5); q and v are 1-term
    const bool two = (MODE == 3) && !is_q && (blockIdx.x < 6);

    auto load_stage = [&](int s, int buf) {
        const int k0 = s * 32;
#pragma unroll
        for (int j = 0; j < 2; j++) {
            const int idx = j * 256 + tid;
            const int r = idx >> 2, c8 = (idx & 3) * 8;
            cpa16(&Ah[buf][r][c8], &Ag[(size_t)(row0 + r) * C_DIM + k0 + c8]);
        }
        {
            const int r = tid >> 2, c8 = (tid & 3) * 8;
            cpa16(&Bh[buf][r][c8], &Whg[(size_t)(col0 + r) * C_DIM + k0 + c8]);
            if (two)
                cpa16(&Bl[buf][r][c8], &Wlg[(size_t)(col0 + r) * C_DIM + k0 + c8]);
        }
    };

    float acc[2][4][4] = {};

    if (MODE == 2) {
        load_stage(0, 0); cpa_commit();
        load_stage(1, 1); cpa_commit();
    } else {
        load_stage(0, 0); cpa_commit();
    }

    for (int s = 0; s < 6; s++) {
        const int buf = s % ST;
        if (MODE == 2) {
            if (s < 4)      { load_stage(s + 2, (s + 2) % 3); cpa_commit(); cpa_wait2(); }
            else if (s == 4) cpa_wait1();
            else             cpa_wait0();
        } else {
            if (s < 5) { load_stage(s + 1, buf ^ 1); cpa_commit(); cpa_wait1(); }
            else       { cpa_wait0(); }
        }
        __syncthreads();

#pragma unroll
        for (int kf = 0; kf < 2; kf++) {
            unsigned ah[2][4];
#pragma unroll
            for (int mf = 0; mf < 2; mf++) {
                unsigned a = smem_u32(&Ah[buf][wm * 32 + mf * 16 + (lane & 15)][kf * 16 + (lane >> 4) * 8]);
                ldsm4(ah[mf][0], ah[mf][1], ah[mf][2], ah[mf][3], a);
            }
            unsigned bh_[4][2], bl_[4][2];
#pragma unroll
            for (int nt2 = 0; nt2 < 2; nt2++) {
                const int rowb = wn * 32 + nt2 * 16 + ((lane >> 4) << 3) + (lane & 7);
                const int colb = kf * 16 + ((lane >> 3) & 1) * 8;
                unsigned r0, r1, r2, r3;
                ldsm4(r0, r1, r2, r3, smem_u32(&Bh[buf][rowb][colb]));
                bh_[nt2 * 2][0] = r0; bh_[nt2 * 2][1] = r1;
                bh_[nt2 * 2 + 1][0] = r2; bh_[nt2 * 2 + 1][1] = r3;
                if (two) {
                    ldsm4(r0, r1, r2, r3, smem_u32(&Bl[buf & 1][rowb][colb]));
                    bl_[nt2 * 2][0] = r0; bl_[nt2 * 2][1] = r1;
                    bl_[nt2 * 2 + 1][0] = r2; bl_[nt2 * 2 + 1][1] = r3;
                }
            }
#pragma unroll
            for (int mf = 0; mf < 2; mf++)
#pragma unroll
                for (int nt = 0; nt < 4; nt++) {
                    mma16816(acc[mf][nt], ah[mf][0], ah[mf][1], ah[mf][2], ah[mf][3], bh_[nt][0], bh_[nt][1]);
                    if (two)
                        mma16816(acc[mf][nt], ah[mf][0], ah[mf][1], ah[mf][2], ah[mf][3], bl_[nt][0], bl_[nt][1]);
                }
        }
        __syncthreads();
    }

    // ---- epilogue ----
    if (MODE == 2) {
#pragma unroll
        for (int mf = 0; mf < 2; mf++) {
            const int rlo = row0 + wm * 32 + mf * 16 + (lane >> 2);
#pragma unroll
            for (int nt = 0; nt < 4; nt++) {
                const int cc = col0 + wn * 32 + nt * 8 + (lane & 3) * 2;
#pragma unroll
                for (int half_ = 0; half_ < 2; half_++) {
                    const int r = rlo + half_ * 8;
                    float2 o = make_float2(acc[mf][nt][half_ * 2 + 0] + bias1[cc],
                                           acc[mf][nt][half_ * 2 + 1] + bias1[cc + 1]);
                    *(float2*)&outf[(size_t)r * C_DIM + cc] = o;
                }
            }
        }
        return;
    }

    const int cbase = col0 + wn * 32;           // 32-aligned
    const bool is_v = !is_q && (cbase >= C_DIM);

    if (is_v) {
        // v columns: add v_b, write transposed [d][n] fp16
#pragma unroll
        for (int mf = 0; mf < 2; mf++) {
            const int rlo = row0 + wm * 32 + mf * 16 + (lane >> 2);
#pragma unroll
            for (int nt = 0; nt < 4; nt++) {
                const int cv = cbase - C_DIM + nt * 8 + (lane & 3) * 2;
                const int h = cv >> 5, d = cv & 31;
#pragma unroll
                for (int half_ = 0; half_ < 2; half_++) {
                    const int r = rlo + half_ * 8;
                    const int b = r >> 9, n = r & 511;
                    const float v0 = acc[mf][nt][half_ * 2 + 0] + bias2[cv];
                    const float v1 = acc[mf][nt][half_ * 2 + 1] + bias2[cv + 1];
                    g_vt[((size_t)(b * HEADS + h) * HD + d) * SEQ + n]     = __float2half_rn(v0);
                    g_vt[((size_t)(b * HEADS + h) * HD + d + 1) * SEQ + n] = __float2half_rn(v1);
                }
            }
        }
        return;
    }

    // q or k columns: fused L2-normalize (+ scale*log2e for q)
    const int h = cbase >> 5;
    float hsc = 1.0f;
    if (is_q) hsc = __expf(fminf(ls[h], LOGIT_MAX)) * LOG2E;

#pragma unroll
    for (int mf = 0; mf < 2; mf++) {
        const int rlo = row0 + wm * 32 + mf * 16 + (lane >> 2);
        float va[4][4];
        float ss0 = 0.f, ss1 = 0.f;
#pragma unroll
        for (int nt = 0; nt < 4; nt++) {
            const int cc = cbase + nt * 8 + (lane & 3) * 2;
            float b0 = 0.f, b1 = 0.f;
            if (is_q) { b0 = bias1[cc]; b1 = bias1[cc + 1]; }
            va[nt][0] = acc[mf][nt][0] + b0;
            va[nt][1] = acc[mf][nt][1] + b1;
            va[nt][2] = acc[mf][nt][2] + b0;
            va[nt][3] = acc[mf][nt][3] + b1;
            ss0 += va[nt][0] * va[nt][0] + va[nt][1] * va[nt][1];
            ss1 += va[nt][2] * va[nt][2] + va[nt][3] * va[nt][3];
        }
        ss0 += __shfl_xor_sync(0xffffffffu, ss0, 1);
        ss0 += __shfl_xor_sync(0xffffffffu, ss0, 2);
        ss1 += __shfl_xor_sync(0xffffffffu, ss1, 1);
        ss1 += __shfl_xor_sync(0xffffffffu, ss1, 2);
        const float inv0 = hsc / fmaxf(sqrtf(ss0), 1e-12f);
        const float inv1 = hsc / fmaxf(sqrtf(ss1), 1e-12f);

#pragma unroll
        for (int half_ = 0; half_ < 2; half_++) {
            const int r = rlo + half_ * 8;
            const int b = r >> 9, n = r & 511;
            const float inv = half_ ? inv1 : inv0;
            const size_t base = (((size_t)(b * HEADS + h) << 9) | n) * HD;
#pragma unroll
            for (int nt = 0; nt < 4; nt++) {
                const int d = nt * 8 + (lane & 3) * 2;
                const float v0 = va[nt][half_ * 2 + 0] * inv;
                const float v1 = va[nt][half_ * 2 + 1] * inv;
                __half* dst = is_q ? g_qh : g_kh;
                *(__half2*)&dst[base + d] = __floats2half2_rn(v0, v1);
            }
        }
    }
}

// ============================================================
// Attention per (b,h). 256 thr, 8 warps, 3 CTA/SM. (R9-proven)
// ============================================================
__device__ __forceinline__ unsigned kswz(int r, int cbytes) {
    return r * 64 + (cbytes ^ ((r & 6) * 8));
}

__global__ __launch_bounds__(256, 3)
void attn_kernel(const float* __restrict__ ls)
{
    extern __shared__ __half sm[];
    __half* Khs = sm;                    // 512 rows x 64B, swizzled
    __half* Vts = sm + 512 * 32;         // [32][520]

    const int bh = blockIdx.x;
    const int b = bh / HEADS, h = bh % HEADS;
    const int tid = threadIdx.x, w = tid >> 5, lane = tid & 31;

    const float bias2 = __expf(fminf(ls[h], LOGIT_MAX)) * LOG2E;

    const __half* kh = g_kh + (size_t)bh * SEQ * HD;
    const __half* vt = g_vt + (size_t)bh * HD * SEQ;

#pragma unroll
    for (int p = 0; p < 8; p++) {
        const int idx = p * 256 + tid;
        const int r = idx >> 2, cb = (idx & 3) * 16;
        *(uint4*)((char*)Khs + kswz(r, cb)) = *(const uint4*)&kh[r * HD + cb / 2];
    }
#pragma unroll
    for (int p = 0; p < 8; p++) {
        const int idx = p * 256 + tid;
        const int d = idx >> 6, c8 = (idx & 63) * 8;
        *(uint4*)&Vts[d * 520 + c8] = *(const uint4*)&vt[d * SEQ + c8];
    }
    __syncthreads();

    const __half* qh = g_qh + (size_t)bh * SEQ * HD;

    for (int mf = 0; mf < 4; mf++) {
        const int m0 = w * 64 + mf * 16;
        const int rlo = m0 + (lane >> 2);

        unsigned qhf[2][4];
#pragma unroll
        for (int kf = 0; kf < 2; kf++) {
            const int kb = kf * 16 + (lane & 3) * 2;
            qhf[kf][0] = *(const unsigned*)&qh[(size_t)rlo * HD + kb];
            qhf[kf][1] = *(const unsigned*)&qh[(size_t)(rlo + 8) * HD + kb];
            qhf[kf][2] = *(const unsigned*)&qh[(size_t)rlo * HD + kb + 8];
            qhf[kf][3] = *(const unsigned*)&qh[(size_t)(rlo + 8) * HD + kb + 8];
        }

        float O[4][4] = {};
        float l_lo = 0.f, l_hi = 0.f;

        for (int kc = 0; kc < 8; kc++) {
            float S[8][4] = {};
#pragma unroll
            for (int nt2 = 0; nt2 < 4; nt2++) {
                const int rowb = kc * 64 + nt2 * 16 + ((lane >> 4) << 3) + (lane & 7);
                const int colb2 = ((lane >> 3) & 1) * 16;
#pragma unroll
                for (int kf = 0; kf < 2; kf++) {
                    const unsigned off = kswz(rowb, kf * 32 + colb2);
                    unsigned kh0, kh1, kh2, kh3;
                    ldsm4(kh0, kh1, kh2, kh3, smem_u32((char*)Khs + off));
                    mma16816(S[nt2 * 2],     qhf[kf][0], qhf[kf][1], qhf[kf][2], qhf[kf][3], kh0, kh1);
                    mma16816(S[nt2 * 2 + 1], qhf[kf][0], qhf[kf][1], qhf[kf][2], qhf[kf][3], kh2, kh3);
                }
            }

#pragma unroll
            for (int nt = 0; nt < 8; nt++) {
                S[nt][0] = ex2(S[nt][0] - bias2);
                S[nt][1] = ex2(S[nt][1] - bias2);
                S[nt][2] = ex2(S[nt][2] - bias2);
                S[nt][3] = ex2(S[nt][3] - bias2);
                l_lo += S[nt][0] + S[nt][1];
                l_hi += S[nt][2] + S[nt][3];
            }

#pragma unroll
            for (int ks = 0; ks < 4; ks++) {
                const unsigned p0 = pack_h2(S[2 * ks][0], S[2 * ks][1]);
                const unsigned p1 = pack_h2(S[2 * ks][2], S[2 * ks][3]);
                const unsigned p2 = pack_h2(S[2 * ks + 1][0], S[2 * ks + 1][1]);
                const unsigned p3 = pack_h2(S[2 * ks + 1][2], S[2 * ks + 1][3]);
#pragma unroll
                for (int dt2 = 0; dt2 < 2; dt2++) {
                    const int rowd = dt2 * 16 + ((lane >> 4) << 3) + (lane & 7);
                    const int colk = kc * 64 + ks * 16 + ((lane >> 3) & 1) * 8;
                    unsigned v0, v1, v2, v3;
                    ldsm4(v0, v1, v2, v3, smem_u32(&Vts[rowd * 520 + colk]));
                    mma16816(O[dt2 * 2],     p0, p1, p2, p3, v0, v1);
                    mma16816(O[dt2 * 2 + 1], p0, p1, p2, p3, v2, v3);
                }
            }
        }

        l_lo += __shfl_xor_sync(0xffffffffu, l_lo, 1);
        l_lo += __shfl_xor_sync(0xffffffffu, l_lo, 2);
        l_hi += __shfl_xor_sync(0xffffffffu, l_hi, 1);
        l_hi += __shfl_xor_sync(0xffffffffu, l_hi, 2);
        const float il_lo = 1.0f / l_lo, il_hi = 1.0f / l_hi;
#pragma unroll
        for (int dt = 0; dt < 4; dt++) {
            __half2 o_lo = __floats2half2_rn(O[dt][0] * il_lo, O[dt][1] * il_lo);
            __half2 o_hi = __floats2half2_rn(O[dt][2] * il_hi, O[dt][3] * il_hi);
            const size_t base = ((size_t)b * SEQ + rlo) * C_DIM + h * HD + dt * 8 + (lane & 3) * 2;
            *(__half2*)&g_attno[base] = o_lo;
            *(__half2*)&g_attno[base + (size_t)8 * C_DIM] = o_hi;
        }
    }
}

// ============================================================
// Launch
// ============================================================
extern "C" void kernel_launch(void* const* d_in, const int* in_sizes, int n_in,
                              void* d_out, int out_size)
{
    (void)in_sizes; (void)n_in; (void)out_size;
    const float* x1     = (const float*)d_in[0];
    const float* x2     = (const float*)d_in[1];
    const float* q_w    = (const float*)d_in[2];
    const float* q_b    = (const float*)d_in[3];
    const float* kv_w   = (const float*)d_in[4];
    const float* v_b    = (const float*)d_in[5];
    const float* ls     = (const float*)d_in[6];
    const float* proj_w = (const float*)d_in[7];
    const float* proj_b = (const float*)d_in[8];
    float* out = (float*)d_out;

    __half *x1h, *x2h, *wqh, *wkvh, *wkvl, *wph, *attno;
    cudaGetSymbolAddress((void**)&x1h,  g_x1h);
    cudaGetSymbolAddress((void**)&x2h,  g_x2h);
    cudaGetSymbolAddress((void**)&wqh,  g_wqh);
    cudaGetSymbolAddress((void**)&wkvh, g_wkvh);
    cudaGetSymbolAddress((void**)&wkvl, g_wkvl);
    cudaGetSymbolAddress((void**)&wph,  g_wph);
    cudaGetSymbolAddress((void**)&attno, g_attno);

    prep_kernel<<<12360, 256>>>(x1, x2, q_w, kv_w, proj_w);

    // fused q + kv projections (q: 1-term, k: 2-term, v: 1-term)
    gemm_kernel<3><<<dim3(9, MROWS / 128), 256>>>(x1h, x2h, wqh, wkvh, wkvl,
                                                  q_b, v_b, ls, nullptr);

    const int smem_bytes = (512 * 32 + 32 * 520) * (int)sizeof(__half); // 66048
    cudaFuncSetAttribute(attn_kernel, cudaFuncAttributeMaxDynamicSharedMemorySize, smem_bytes);
    attn_kernel<<<BH, 256, smem_bytes>>>(ls);

    // output projection (1-term, 3-stage pipeline)
    gemm_kernel<2><<<dim3(3, MROWS / 128), 256>>>(attno, nullptr, wph, nullptr, nullptr,
                                                  proj_b, nullptr, nullptr, out);
}

// round 16
// speedup vs baseline: 1.5615x; 1.0043x over previous
#include <cuda_runtime.h>
#include <cuda_fp16.h>

#define C_DIM 192
#define HEADS 6
#define HD 32
#define BATCH 128
#define SEQ 512
#define MROWS (BATCH * SEQ)        // 65536
#define BH (BATCH * HEADS)         // 768
#define LOGIT_MAX 4.6051701859880914f
#define LOG2E 1.4426950408889634f

// ---------------- device-global scratch ----------------
__device__ __half g_qh[(size_t)BH * SEQ * HD];    // normalized * scale * log2e q
__device__ __half g_kh[(size_t)BH * SEQ * HD];    // normalized k
__device__ __half g_vt[(size_t)BH * HD * SEQ];    // v transposed per (b,h): [d][n]
__device__ __half g_attno[(size_t)MROWS * C_DIM];
__device__ __half g_x1h[(size_t)MROWS * C_DIM];
__device__ __half g_x2h[(size_t)MROWS * C_DIM];
__device__ __half g_wqh[C_DIM * C_DIM];
__device__ __half g_wkvh[2 * C_DIM * C_DIM];
__device__ __half g_wkvl[2 * C_DIM * C_DIM];
__device__ __half g_wph[C_DIM * C_DIM];

// ---------------- helpers ----------------
__device__ __forceinline__ unsigned smem_u32(const void* p) {
    return (unsigned)__cvta_generic_to_shared(p);
}
__device__ __forceinline__ void ldsm4(unsigned& r0, unsigned& r1, unsigned& r2, unsigned& r3, unsigned a) {
    asm volatile("ldmatrix.sync.aligned.m8n8.x4.shared.b16 {%0,%1,%2,%3},[%4];\n"
                 : "=r"(r0), "=r"(r1), "=r"(r2), "=r"(r3) : "r"(a));
}
__device__ __forceinline__ void mma16816(float* c, unsigned a0, unsigned a1, unsigned a2, unsigned a3,
                                         unsigned b0, unsigned b1) {
    asm volatile("mma.sync.aligned.m16n8k16.row.col.f32.f16.f16.f32 "
                 "{%0,%1,%2,%3},{%4,%5,%6,%7},{%8,%9},{%0,%1,%2,%3};\n"
                 : "+f"(c[0]), "+f"(c[1]), "+f"(c[2]), "+f"(c[3])
                 : "r"(a0), "r"(a1), "r"(a2), "r"(a3), "r"(b0), "r"(b1));
}
__device__ __forceinline__ void split2(float x, float y, __half2& hi, __half2& lo) {
    __half hx = __float2half_rn(x), hy = __float2half_rn(y);
    hi = __halves2half2(hx, hy);
    lo = __floats2half2_rn(x - __half2float(hx), y - __half2float(hy));
}
__device__ __forceinline__ unsigned pack_h2(float a, float b) {
    __half2 t = __floats2half2_rn(a, b);
    return *(unsigned*)&t;
}
__device__ __forceinline__ float ex2(float x) {
    float y;
    asm("ex2.approx.ftz.f32 %0, %1;" : "=f"(y) : "f"(x));
    return y;
}
__device__ __forceinline__ void cpa16(void* s, const void* g) {
    asm volatile("cp.async.ca.shared.global [%0], [%1], 16;\n" :: "r"(smem_u32(s)), "l"(g));
}
__device__ __forceinline__ void cpa_commit() { asm volatile("cp.async.commit_group;\n"); }
__device__ __forceinline__ void cpa_wait1()  { asm volatile("cp.async.wait_group 1;\n"); }
__device__ __forceinline__ void cpa_wait0()  { asm volatile("cp.async.wait_group 0;\n"); }

// ============================================================
// Combined prep: x1/x2 fp32->fp16 (blocks < 12288) and
// weight prep (blocks 12288..12359: q hi, kv split, proj hi).
// ============================================================
__global__ __launch_bounds__(256)
void prep_kernel(const float* __restrict__ x1, const float* __restrict__ x2,
                 const float* __restrict__ qw, const float* __restrict__ kvw,
                 const float* __restrict__ pw)
{
    int blk = blockIdx.x;
    if (blk < 12288) {
        const float* src;  __half* dst;
        if (blk < 6144) { src = x1; dst = g_x1h; }
        else            { src = x2; dst = g_x2h; blk -= 6144; }
        const int i = blk * 256 + threadIdx.x;
        const float4 a = *(const float4*)&src[(size_t)i * 8];
        const float4 b = *(const float4*)&src[(size_t)i * 8 + 4];
        __half2 h[4];
        h[0] = __floats2half2_rn(a.x, a.y);
        h[1] = __floats2half2_rn(a.z, a.w);
        h[2] = __floats2half2_rn(b.x, b.y);
        h[3] = __floats2half2_rn(b.z, b.w);
        *(uint4*)&dst[(size_t)i * 8] = *(uint4*)h;
        return;
    }
    blk -= 12288;
    if (blk >= 18 && blk < 54) {            // kv: split
        const int i = (blk - 18) * 256 + threadIdx.x;
        const float4 a = *(const float4*)&kvw[(size_t)i * 8];
        const float4 b = *(const float4*)&kvw[(size_t)i * 8 + 4];
        __half2 h[4], l[4];
        split2(a.x, a.y, h[0], l[0]);
        split2(a.z, a.w, h[1], l[1]);
        split2(b.x, b.y, h[2], l[2]);
        split2(b.z, b.w, h[3], l[3]);
        *(uint4*)&g_wkvh[(size_t)i * 8] = *(uint4*)h;
        *(uint4*)&g_wkvl[(size_t)i * 8] = *(uint4*)l;
    } else {                                 // q / proj: plain fp16
        const float* src;  __half* dst;
        if (blk < 18) { src = qw; dst = g_wqh; }
        else          { src = pw; dst = g_wph; blk -= 54; }
        const int i = blk * 256 + threadIdx.x;
        const float4 a = *(const float4*)&src[(size_t)i * 8];
        const float4 b = *(const float4*)&src[(size_t)i * 8 + 4];
        __half2 h[4];
        h[0] = __floats2half2_rn(a.x, a.y);
        h[1] = __floats2half2_rn(a.z, a.w);
        h[2] = __floats2half2_rn(b.x, b.y);
        h[3] = __floats2half2_rn(b.z, b.w);
        *(uint4*)&dst[(size_t)i * 8] = *(uint4*)h;
    }
}

// ============================================================
// Fused q+kv tensor-core GEMM (R12/R14-proven). BM=128, BN=64,
// BK=32, 2-stage, 8 warps.
//   bx<3:   q (x1h @ wqh, 1-term) -> +q_b, L2-norm, *exp(ls)*log2e -> g_qh
//   bx 3-5: k (x2h @ wkvh+wkvl, 2-term) -> L2-norm -> g_kh
//   bx 6-8: v (x2h @ wkvh, 1-term)      -> +v_b -> g_vt^T
// ============================================================
__global__ __launch_bounds__(256)
void qkv_kernel(const __half* __restrict__ A1, const __half* __restrict__ A2,
                const __half* __restrict__ Wq, const __half* __restrict__ Wkvh,
                const __half* __restrict__ Wkvl,
                const float* __restrict__ bias1, const float* __restrict__ bias2,
                const float* __restrict__ ls)
{
    __shared__ __half Ah[2][128][40];
    __shared__ __half Bh[2][64][40];
    __shared__ __half Bl[2][64][40];

    const int tid = threadIdx.x, w = tid >> 5, lane = tid & 31;
    const int wm = w >> 1, wn = w & 1;
    const int row0 = blockIdx.y * 128;

    const bool is_q = (blockIdx.x < 3);
    const int col0 = (is_q ? blockIdx.x : blockIdx.x - 3) * 64;
    const __half* Ag  = is_q ? A1 : A2;
    const __half* Whg = is_q ? Wq : Wkvh;
    const __half* Wlg = Wkvl;
    const bool two = !is_q && (blockIdx.x < 6);   // k blocks only

    auto load_stage = [&](int s, int buf) {
        const int k0 = s * 32;
#pragma unroll
        for (int j = 0; j < 2; j++) {
            const int idx = j * 256 + tid;
            const int r = idx >> 2, c8 = (idx & 3) * 8;
            cpa16(&Ah[buf][r][c8], &Ag[(size_t)(row0 + r) * C_DIM + k0 + c8]);
        }
        {
            const int r = tid >> 2, c8 = (tid & 3) * 8;
            cpa16(&Bh[buf][r][c8], &Whg[(size_t)(col0 + r) * C_DIM + k0 + c8]);
            if (two)
                cpa16(&Bl[buf][r][c8], &Wlg[(size_t)(col0 + r) * C_DIM + k0 + c8]);
        }
    };

    float acc[2][4][4] = {};

    load_stage(0, 0);
    cpa_commit();

    for (int s = 0; s < 6; s++) {
        const int buf = s & 1;
        if (s < 5) { load_stage(s + 1, buf ^ 1); cpa_commit(); cpa_wait1(); }
        else       { cpa_wait0(); }
        __syncthreads();

#pragma unroll
        for (int kf = 0; kf < 2; kf++) {
            unsigned ah[2][4];
#pragma unroll
            for (int mf = 0; mf < 2; mf++) {
                unsigned a = smem_u32(&Ah[buf][wm * 32 + mf * 16 + (lane & 15)][kf * 16 + (lane >> 4) * 8]);
                ldsm4(ah[mf][0], ah[mf][1], ah[mf][2], ah[mf][3], a);
            }
            unsigned bh_[4][2], bl_[4][2];
#pragma unroll
            for (int nt2 = 0; nt2 < 2; nt2++) {
                const int rowb = wn * 32 + nt2 * 16 + ((lane >> 4) << 3) + (lane & 7);
                const int colb = kf * 16 + ((lane >> 3) & 1) * 8;
                unsigned r0, r1, r2, r3;
                ldsm4(r0, r1, r2, r3, smem_u32(&Bh[buf][rowb][colb]));
                bh_[nt2 * 2][0] = r0; bh_[nt2 * 2][1] = r1;
                bh_[nt2 * 2 + 1][0] = r2; bh_[nt2 * 2 + 1][1] = r3;
                if (two) {
                    ldsm4(r0, r1, r2, r3, smem_u32(&Bl[buf][rowb][colb]));
                    bl_[nt2 * 2][0] = r0; bl_[nt2 * 2][1] = r1;
                    bl_[nt2 * 2 + 1][0] = r2; bl_[nt2 * 2 + 1][1] = r3;
                }
            }
#pragma unroll
            for (int mf = 0; mf < 2; mf++)
#pragma unroll
                for (int nt = 0; nt < 4; nt++) {
                    mma16816(acc[mf][nt], ah[mf][0], ah[mf][1], ah[mf][2], ah[mf][3], bh_[nt][0], bh_[nt][1]);
                    if (two)
                        mma16816(acc[mf][nt], ah[mf][0], ah[mf][1], ah[mf][2], ah[mf][3], bl_[nt][0], bl_[nt][1]);
                }
        }
        __syncthreads();
    }

    const int cbase = col0 + wn * 32;           // 32-aligned
    const bool is_v = !is_q && (cbase >= C_DIM);

    if (is_v) {
        // v columns: add v_b, write transposed [d][n] fp16
#pragma unroll
        for (int mf = 0; mf < 2; mf++) {
            const int rlo = row0 + wm * 32 + mf * 16 + (lane >> 2);
#pragma unroll
            for (int nt = 0; nt < 4; nt++) {
                const int cv = cbase - C_DIM + nt * 8 + (lane & 3) * 2;
                const int h = cv >> 5, d = cv & 31;
#pragma unroll
                for (int half_ = 0; half_ < 2; half_++) {
                    const int r = rlo + half_ * 8;
                    const int b = r >> 9, n = r & 511;
                    const float v0 = acc[mf][nt][half_ * 2 + 0] + bias2[cv];
                    const float v1 = acc[mf][nt][half_ * 2 + 1] + bias2[cv + 1];
                    g_vt[((size_t)(b * HEADS + h) * HD + d) * SEQ + n]     = __float2half_rn(v0);
                    g_vt[((size_t)(b * HEADS + h) * HD + d + 1) * SEQ + n] = __float2half_rn(v1);
                }
            }
        }
        return;
    }

    // q or k columns: fused L2-normalize (+ scale*log2e for q)
    const int h = cbase >> 5;
    float hsc = 1.0f;
    if (is_q) hsc = __expf(fminf(ls[h], LOGIT_MAX)) * LOG2E;

#pragma unroll
    for (int mf = 0; mf < 2; mf++) {
        const int rlo = row0 + wm * 32 + mf * 16 + (lane >> 2);
        float va[4][4];
        float ss0 = 0.f, ss1 = 0.f;
#pragma unroll
        for (int nt = 0; nt < 4; nt++) {
            const int cc = cbase + nt * 8 + (lane & 3) * 2;
            float b0 = 0.f, b1 = 0.f;
            if (is_q) { b0 = bias1[cc]; b1 = bias1[cc + 1]; }
            va[nt][0] = acc[mf][nt][0] + b0;
            va[nt][1] = acc[mf][nt][1] + b1;
            va[nt][2] = acc[mf][nt][2] + b0;
            va[nt][3] = acc[mf][nt][3] + b1;
            ss0 += va[nt][0] * va[nt][0] + va[nt][1] * va[nt][1];
            ss1 += va[nt][2] * va[nt][2] + va[nt][3] * va[nt][3];
        }
        ss0 += __shfl_xor_sync(0xffffffffu, ss0, 1);
        ss0 += __shfl_xor_sync(0xffffffffu, ss0, 2);
        ss1 += __shfl_xor_sync(0xffffffffu, ss1, 1);
        ss1 += __shfl_xor_sync(0xffffffffu, ss1, 2);
        const float inv0 = hsc / fmaxf(sqrtf(ss0), 1e-12f);
        const float inv1 = hsc / fmaxf(sqrtf(ss1), 1e-12f);

#pragma unroll
        for (int half_ = 0; half_ < 2; half_++) {
            const int r = rlo + half_ * 8;
            const int b = r >> 9, n = r & 511;
            const float inv = half_ ? inv1 : inv0;
            const size_t base = (((size_t)(b * HEADS + h) << 9) | n) * HD;
#pragma unroll
            for (int nt = 0; nt < 4; nt++) {
                const int d = nt * 8 + (lane & 3) * 2;
                const float v0 = va[nt][half_ * 2 + 0] * inv;
                const float v1 = va[nt][half_ * 2 + 1] * inv;
                __half* dst = is_q ? g_qh : g_kh;
                *(__half2*)&dst[base + d] = __floats2half2_rn(v0, v1);
            }
        }
    }
}

// ============================================================
// Output projection: BM=256, BN=64, BK=32, 2-stage, 1-term
// (R10-proven BM=256 body). 8 warps (4m x 2n), warp tile 64x32.
// Dynamic smem 51200 B -> 2 CTAs/SM.
// ============================================================
#define PA_OFF 0                       // [2][256][40] halves
#define PB_OFF (2 * 256 * 40)          // [2][64][40]
#define PROJ_SMEM ((PB_OFF + 2 * 64 * 40) * 2)   // 51200 bytes

__global__ __launch_bounds__(256, 2)
void proj_kernel(const __half* __restrict__ Ag, const __half* __restrict__ Wg,
                 const float* __restrict__ bias, float* __restrict__ outf)
{
    extern __shared__ __half smx[];
    __half* Ahs = smx + PA_OFF;
    __half* Bhs = smx + PB_OFF;

    const int tid = threadIdx.x, w = tid >> 5, lane = tid & 31;
    const int wm = w >> 1, wn = w & 1;
    const int row0 = blockIdx.y * 256, col0 = blockIdx.x * 64;

    auto load_stage = [&](int s, int buf) {
        const int k0 = s * 32;
        __half* Ab = Ahs + buf * 256 * 40;
#pragma unroll
        for (int j = 0; j < 4; j++) {
            const int idx = j * 256 + tid;
            const int r = idx >> 2, c8 = (idx & 3) * 8;
            cpa16(&Ab[r * 40 + c8], &Ag[(size_t)(row0 + r) * C_DIM + k0 + c8]);
        }
        {
            const int r = tid >> 2, c8 = (tid & 3) * 8;
            cpa16(&Bhs[buf * 64 * 40 + r * 40 + c8], &Wg[(size_t)(col0 + r) * C_DIM + k0 + c8]);
        }
    };

    float acc[4][4][4] = {};

    load_stage(0, 0);
    cpa_commit();

    for (int s = 0; s < 6; s++) {
        const int buf = s & 1;
        if (s < 5) { load_stage(s + 1, buf ^ 1); cpa_commit(); cpa_wait1(); }
        else       { cpa_wait0(); }
        __syncthreads();

        __half* Ab = Ahs + buf * 256 * 40;
#pragma unroll
        for (int kf = 0; kf < 2; kf++) {
            unsigned ah[4][4];
#pragma unroll
            for (int mf = 0; mf < 4; mf++) {
                unsigned a = smem_u32(&Ab[(wm * 64 + mf * 16 + (lane & 15)) * 40 + kf * 16 + (lane >> 4) * 8]);
                ldsm4(ah[mf][0], ah[mf][1], ah[mf][2], ah[mf][3], a);
            }
            unsigned bh_[4][2];
#pragma unroll
            for (int nt2 = 0; nt2 < 2; nt2++) {
                const int rowb = wn * 32 + nt2 * 16 + ((lane >> 4) << 3) + (lane & 7);
                const int colb = kf * 16 + ((lane >> 3) & 1) * 8;
                unsigned r0, r1, r2, r3;
                ldsm4(r0, r1, r2, r3, smem_u32(&Bhs[buf * 64 * 40 + rowb * 40 + colb]));
                bh_[nt2 * 2][0] = r0; bh_[nt2 * 2][1] = r1;
                bh_[nt2 * 2 + 1][0] = r2; bh_[nt2 * 2 + 1][1] = r3;
            }
#pragma unroll
            for (int mf = 0; mf < 4; mf++)
#pragma unroll
                for (int nt = 0; nt < 4; nt++)
                    mma16816(acc[mf][nt], ah[mf][0], ah[mf][1], ah[mf][2], ah[mf][3], bh_[nt][0], bh_[nt][1]);
        }
        __syncthreads();
    }

#pragma unroll
    for (int mf = 0; mf < 4; mf++) {
        const int rlo = row0 + wm * 64 + mf * 16 + (lane >> 2);
#pragma unroll
        for (int nt = 0; nt < 4; nt++) {
            const int cc = col0 + wn * 32 + nt * 8 + (lane & 3) * 2;
#pragma unroll
            for (int half_ = 0; half_ < 2; half_++) {
                const int r = rlo + half_ * 8;
                float2 o = make_float2(acc[mf][nt][half_ * 2 + 0] + bias[cc],
                                       acc[mf][nt][half_ * 2 + 1] + bias[cc + 1]);
                *(float2*)&outf[(size_t)r * C_DIM + cc] = o;
            }
        }
    }
}

// ============================================================
// Attention per (b,h). 256 thr, 8 warps, 3 CTA/SM. (R9-proven)
// ============================================================
__device__ __forceinline__ unsigned kswz(int r, int cbytes) {
    return r * 64 + (cbytes ^ ((r & 6) * 8));
}

__global__ __launch_bounds__(256, 3)
void attn_kernel(const float* __restrict__ ls)
{
    extern __shared__ __half sm[];
    __half* Khs = sm;                    // 512 rows x 64B, swizzled
    __half* Vts = sm + 512 * 32;         // [32][520]

    const int bh = blockIdx.x;
    const int b = bh / HEADS, h = bh % HEADS;
    const int tid = threadIdx.x, w = tid >> 5, lane = tid & 31;

    const float bias2 = __expf(fminf(ls[h], LOGIT_MAX)) * LOG2E;

    const __half* kh = g_kh + (size_t)bh * SEQ * HD;
    const __half* vt = g_vt + (size_t)bh * HD * SEQ;

#pragma unroll
    for (int p = 0; p < 8; p++) {
        const int idx = p * 256 + tid;
        const int r = idx >> 2, cb = (idx & 3) * 16;
        *(uint4*)((char*)Khs + kswz(r, cb)) = *(const uint4*)&kh[r * HD + cb / 2];
    }
#pragma unroll
    for (int p = 0; p < 8; p++) {
        const int idx = p * 256 + tid;
        const int d = idx >> 6, c8 = (idx & 63) * 8;
        *(uint4*)&Vts[d * 520 + c8] = *(const uint4*)&vt[d * SEQ + c8];
    }
    __syncthreads();

    const __half* qh = g_qh + (size_t)bh * SEQ * HD;

    for (int mf = 0; mf < 4; mf++) {
        const int m0 = w * 64 + mf * 16;
        const int rlo = m0 + (lane >> 2);

        unsigned qhf[2][4];
#pragma unroll
        for (int kf = 0; kf < 2; kf++) {
            const int kb = kf * 16 + (lane & 3) * 2;
            qhf[kf][0] = *(const unsigned*)&qh[(size_t)rlo * HD + kb];
            qhf[kf][1] = *(const unsigned*)&qh[(size_t)(rlo + 8) * HD + kb];
            qhf[kf][2] = *(const unsigned*)&qh[(size_t)rlo * HD + kb + 8];
            qhf[kf][3] = *(const unsigned*)&qh[(size_t)(rlo + 8) * HD + kb + 8];
        }

        float O[4][4] = {};
        float l_lo = 0.f, l_hi = 0.f;

        for (int kc = 0; kc < 8; kc++) {
            float S[8][4] = {};
#pragma unroll
            for (int nt2 = 0; nt2 < 4; nt2++) {
                const int rowb = kc * 64 + nt2 * 16 + ((lane >> 4) << 3) + (lane & 7);
                const int colb2 = ((lane >> 3) & 1) * 16;
#pragma unroll
                for (int kf = 0; kf < 2; kf++) {
                    const unsigned off = kswz(rowb, kf * 32 + colb2);
                    unsigned kh0, kh1, kh2, kh3;
                    ldsm4(kh0, kh1, kh2, kh3, smem_u32((char*)Khs + off));
                    mma16816(S[nt2 * 2],     qhf[kf][0], qhf[kf][1], qhf[kf][2], qhf[kf][3], kh0, kh1);
                    mma16816(S[nt2 * 2 + 1], qhf[kf][0], qhf[kf][1], qhf[kf][2], qhf[kf][3], kh2, kh3);
                }
            }

#pragma unroll
            for (int nt = 0; nt < 8; nt++) {
                S[nt][0] = ex2(S[nt][0] - bias2);
                S[nt][1] = ex2(S[nt][1] - bias2);
                S[nt][2] = ex2(S[nt][2] - bias2);
                S[nt][3] = ex2(S[nt][3] - bias2);
                l_lo += S[nt][0] + S[nt][1];
                l_hi += S[nt][2] + S[nt][3];
            }

#pragma unroll
            for (int ks = 0; ks < 4; ks++) {
                const unsigned p0 = pack_h2(S[2 * ks][0], S[2 * ks][1]);
                const unsigned p1 = pack_h2(S[2 * ks][2], S[2 * ks][3]);
                const unsigned p2 = pack_h2(S[2 * ks + 1][0], S[2 * ks + 1][1]);
                const unsigned p3 = pack_h2(S[2 * ks + 1][2], S[2 * ks + 1][3]);
#pragma unroll
                for (int dt2 = 0; dt2 < 2; dt2++) {
                    const int rowd = dt2 * 16 + ((lane >> 4) << 3) + (lane & 7);
                    const int colk = kc * 64 + ks * 16 + ((lane >> 3) & 1) * 8;
                    unsigned v0, v1, v2, v3;
                    ldsm4(v0, v1, v2, v3, smem_u32(&Vts[rowd * 520 + colk]));
                    mma16816(O[dt2 * 2],     p0, p1, p2, p3, v0, v1);
                    mma16816(O[dt2 * 2 + 1], p0, p1, p2, p3, v2, v3);
                }
            }
        }

        l_lo += __shfl_xor_sync(0xffffffffu, l_lo, 1);
        l_lo += __shfl_xor_sync(0xffffffffu, l_lo, 2);
        l_hi += __shfl_xor_sync(0xffffffffu, l_hi, 1);
        l_hi += __shfl_xor_sync(0xffffffffu, l_hi, 2);
        const float il_lo = 1.0f / l_lo, il_hi = 1.0f / l_hi;
#pragma unroll
        for (int dt = 0; dt < 4; dt++) {
            __half2 o_lo = __floats2half2_rn(O[dt][0] * il_lo, O[dt][1] * il_lo);
            __half2 o_hi = __floats2half2_rn(O[dt][2] * il_hi, O[dt][3] * il_hi);
            const size_t base = ((size_t)b * SEQ + rlo) * C_DIM + h * HD + dt * 8 + (lane & 3) * 2;
            *(__half2*)&g_attno[base] = o_lo;
            *(__half2*)&g_attno[base + (size_t)8 * C_DIM] = o_hi;
        }
    }
}

// ============================================================
// Launch
// ============================================================
extern "C" void kernel_launch(void* const* d_in, const int* in_sizes, int n_in,
                              void* d_out, int out_size)
{
    (void)in_sizes; (void)n_in; (void)out_size;
    const float* x1     = (const float*)d_in[0];
    const float* x2     = (const float*)d_in[1];
    const float* q_w    = (const float*)d_in[2];
    const float* q_b    = (const float*)d_in[3];
    const float* kv_w   = (const float*)d_in[4];
    const float* v_b    = (const float*)d_in[5];
    const float* ls     = (const float*)d_in[6];
    const float* proj_w = (const float*)d_in[7];
    const float* proj_b = (const float*)d_in[8];
    float* out = (float*)d_out;

    __half *x1h, *x2h, *wqh, *wkvh, *wkvl, *wph, *attno;
    cudaGetSymbolAddress((void**)&x1h,  g_x1h);
    cudaGetSymbolAddress((void**)&x2h,  g_x2h);
    cudaGetSymbolAddress((void**)&wqh,  g_wqh);
    cudaGetSymbolAddress((void**)&wkvh, g_wkvh);
    cudaGetSymbolAddress((void**)&wkvl, g_wkvl);
    cudaGetSymbolAddress((void**)&wph,  g_wph);
    cudaGetSymbolAddress((void**)&attno, g_attno);

    prep_kernel<<<12360, 256>>>(x1, x2, q_w, kv_w, proj_w);

    // fused q + kv projections (q: 1-term, k: 2-term, v: 1-term)
    qkv_kernel<<<dim3(9, MROWS / 128), 256>>>(x1h, x2h, wqh, wkvh, wkvl, q_b, v_b, ls);

    const int smem_bytes = (512 * 32 + 32 * 520) * (int)sizeof(__half); // 66048
    cudaFuncSetAttribute(attn_kernel, cudaFuncAttributeMaxDynamicSharedMemorySize, smem_bytes);
    attn_kernel<<<BH, 256, smem_bytes>>>(ls);

    // output projection (BM=256, latency-optimized)
    cudaFuncSetAttribute(proj_kernel, cudaFuncAttributeMaxDynamicSharedMemorySize, PROJ_SMEM);
    proj_kernel<<<dim3(3, MROWS / 256), 256, PROJ_SMEM>>>(attno, wph, proj_b, out);
}

// round 17
// speedup vs baseline: 1.6919x; 1.0835x over previous
#include <cuda_runtime.h>
#include <cuda_fp16.h>

#define C_DIM 192
#define HEADS 6
#define HD 32
#define BATCH 128
#define SEQ 512
#define MROWS (BATCH * SEQ)        // 65536
#define BH (BATCH * HEADS)         // 768
#define LOGIT_MAX 4.6051701859880914f
#define LOG2E 1.4426950408889634f

// ---------------- device-global scratch ----------------
__device__ __half g_qh[(size_t)BH * SEQ * HD];    // normalized * scale * log2e q
__device__ __half g_kh[(size_t)BH * SEQ * HD];    // normalized k
__device__ __half g_vt[(size_t)BH * HD * SEQ];    // v transposed per (b,h): [d][n]
__device__ __half g_attno[(size_t)MROWS * C_DIM];
__device__ __half g_x1h[(size_t)MROWS * C_DIM];
__device__ __half g_x2h[(size_t)MROWS * C_DIM];
__device__ __half g_wqh[C_DIM * C_DIM];
__device__ __half g_wkvh[2 * C_DIM * C_DIM];
__device__ __half g_wph[C_DIM * C_DIM];

// ---------------- helpers ----------------
__device__ __forceinline__ unsigned smem_u32(const void* p) {
    return (unsigned)__cvta_generic_to_shared(p);
}
__device__ __forceinline__ void ldsm4(unsigned& r0, unsigned& r1, unsigned& r2, unsigned& r3, unsigned a) {
    asm volatile("ldmatrix.sync.aligned.m8n8.x4.shared.b16 {%0,%1,%2,%3},[%4];\n"
                 : "=r"(r0), "=r"(r1), "=r"(r2), "=r"(r3) : "r"(a));
}
__device__ __forceinline__ void mma16816(float* c, unsigned a0, unsigned a1, unsigned a2, unsigned a3,
                                         unsigned b0, unsigned b1) {
    asm volatile("mma.sync.aligned.m16n8k16.row.col.f32.f16.f16.f32 "
                 "{%0,%1,%2,%3},{%4,%5,%6,%7},{%8,%9},{%0,%1,%2,%3};\n"
                 : "+f"(c[0]), "+f"(c[1]), "+f"(c[2]), "+f"(c[3])
                 : "r"(a0), "r"(a1), "r"(a2), "r"(a3), "r"(b0), "r"(b1));
}
__device__ __forceinline__ unsigned pack_h2(float a, float b) {
    __half2 t = __floats2half2_rn(a, b);
    return *(unsigned*)&t;
}
__device__ __forceinline__ float ex2(float x) {
    float y;
    asm("ex2.approx.ftz.f32 %0, %1;" : "=f"(y) : "f"(x));
    return y;
}
__device__ __forceinline__ void cpa16(void* s, const void* g) {
    asm volatile("cp.async.ca.shared.global [%0], [%1], 16;\n" :: "r"(smem_u32(s)), "l"(g));
}
__device__ __forceinline__ void cpa_commit() { asm volatile("cp.async.commit_group;\n"); }
__device__ __forceinline__ void cpa_wait1()  { asm volatile("cp.async.wait_group 1;\n"); }
__device__ __forceinline__ void cpa_wait0()  { asm volatile("cp.async.wait_group 0;\n"); }

// ============================================================
// Combined prep: all fp32 -> fp16 (inputs + all weights, single-term).
// blocks: [0,6144) x1, [6144,12288) x2,
//         [12288,12306) q_w, [12306,12342) kv_w, [12342,12360) proj_w.
// ============================================================
__global__ __launch_bounds__(256)
void prep_kernel(const float* __restrict__ x1, const float* __restrict__ x2,
                 const float* __restrict__ qw, const float* __restrict__ kvw,
                 const float* __restrict__ pw)
{
    int blk = blockIdx.x;
    const float* src;  __half* dst;
    if (blk < 6144)        { src = x1;  dst = g_x1h; }
    else if (blk < 12288)  { src = x2;  dst = g_x2h;  blk -= 6144; }
    else if (blk < 12306)  { src = qw;  dst = g_wqh;  blk -= 12288; }
    else if (blk < 12342)  { src = kvw; dst = g_wkvh; blk -= 12306; }
    else                   { src = pw;  dst = g_wph;  blk -= 12342; }
    const int i = blk * 256 + threadIdx.x;
    const float4 a = *(const float4*)&src[(size_t)i * 8];
    const float4 b = *(const float4*)&src[(size_t)i * 8 + 4];
    __half2 h[4];
    h[0] = __floats2half2_rn(a.x, a.y);
    h[1] = __floats2half2_rn(a.z, a.w);
    h[2] = __floats2half2_rn(b.x, b.y);
    h[3] = __floats2half2_rn(b.z, b.w);
    *(uint4*)&dst[(size_t)i * 8] = *(uint4*)h;
}

// ============================================================
// Fused q+kv tensor-core GEMM, all single-term fp16.
// BM=128, BN=64, BK=32, 2-stage, 8 warps.
//   bx<3:   q (x1h @ wqh) -> +q_b, L2-norm, *exp(ls)*log2e -> g_qh
//   bx 3-5: k (x2h @ wkvh) -> L2-norm -> g_kh
//   bx 6-8: v (x2h @ wkvh) -> +v_b -> g_vt^T
// ============================================================
__global__ __launch_bounds__(256)
void qkv_kernel(const __half* __restrict__ A1, const __half* __restrict__ A2,
                const __half* __restrict__ Wq, const __half* __restrict__ Wkvh,
                const float* __restrict__ bias1, const float* __restrict__ bias2,
                const float* __restrict__ ls)
{
    __shared__ __half Ah[2][128][40];
    __shared__ __half Bh[2][64][40];

    const int tid = threadIdx.x, w = tid >> 5, lane = tid & 31;
    const int wm = w >> 1, wn = w & 1;
    const int row0 = blockIdx.y * 128;

    const bool is_q = (blockIdx.x < 3);
    const int col0 = (is_q ? blockIdx.x : blockIdx.x - 3) * 64;
    const __half* Ag  = is_q ? A1 : A2;
    const __half* Whg = is_q ? Wq : Wkvh;

    auto load_stage = [&](int s, int buf) {
        const int k0 = s * 32;
#pragma unroll
        for (int j = 0; j < 2; j++) {
            const int idx = j * 256 + tid;
            const int r = idx >> 2, c8 = (idx & 3) * 8;
            cpa16(&Ah[buf][r][c8], &Ag[(size_t)(row0 + r) * C_DIM + k0 + c8]);
        }
        {
            const int r = tid >> 2, c8 = (tid & 3) * 8;
            cpa16(&Bh[buf][r][c8], &Whg[(size_t)(col0 + r) * C_DIM + k0 + c8]);
        }
    };

    float acc[2][4][4] = {};

    load_stage(0, 0);
    cpa_commit();

    for (int s = 0; s < 6; s++) {
        const int buf = s & 1;
        if (s < 5) { load_stage(s + 1, buf ^ 1); cpa_commit(); cpa_wait1(); }
        else       { cpa_wait0(); }
        __syncthreads();

#pragma unroll
        for (int kf = 0; kf < 2; kf++) {
            unsigned ah[2][4];
#pragma unroll
            for (int mf = 0; mf < 2; mf++) {
                unsigned a = smem_u32(&Ah[buf][wm * 32 + mf * 16 + (lane & 15)][kf * 16 + (lane >> 4) * 8]);
                ldsm4(ah[mf][0], ah[mf][1], ah[mf][2], ah[mf][3], a);
            }
            unsigned bh_[4][2];
#pragma unroll
            for (int nt2 = 0; nt2 < 2; nt2++) {
                const int rowb = wn * 32 + nt2 * 16 + ((lane >> 4) << 3) + (lane & 7);
                const int colb = kf * 16 + ((lane >> 3) & 1) * 8;
                unsigned r0, r1, r2, r3;
                ldsm4(r0, r1, r2, r3, smem_u32(&Bh[buf][rowb][colb]));
                bh_[nt2 * 2][0] = r0; bh_[nt2 * 2][1] = r1;
                bh_[nt2 * 2 + 1][0] = r2; bh_[nt2 * 2 + 1][1] = r3;
            }
#pragma unroll
            for (int mf = 0; mf < 2; mf++)
#pragma unroll
                for (int nt = 0; nt < 4; nt++)
                    mma16816(acc[mf][nt], ah[mf][0], ah[mf][1], ah[mf][2], ah[mf][3], bh_[nt][0], bh_[nt][1]);
        }
        __syncthreads();
    }

    const int cbase = col0 + wn * 32;           // 32-aligned
    const bool is_v = !is_q && (cbase >= C_DIM);

    if (is_v) {
        // v columns: add v_b, write transposed [d][n] fp16
#pragma unroll
        for (int mf = 0; mf < 2; mf++) {
            const int rlo = row0 + wm * 32 + mf * 16 + (lane >> 2);
#pragma unroll
            for (int nt = 0; nt < 4; nt++) {
                const int cv = cbase - C_DIM + nt * 8 + (lane & 3) * 2;
                const int h = cv >> 5, d = cv & 31;
#pragma unroll
                for (int half_ = 0; half_ < 2; half_++) {
                    const int r = rlo + half_ * 8;
                    const int b = r >> 9, n = r & 511;
                    const float v0 = acc[mf][nt][half_ * 2 + 0] + bias2[cv];
                    const float v1 = acc[mf][nt][half_ * 2 + 1] + bias2[cv + 1];
                    g_vt[((size_t)(b * HEADS + h) * HD + d) * SEQ + n]     = __float2half_rn(v0);
                    g_vt[((size_t)(b * HEADS + h) * HD + d + 1) * SEQ + n] = __float2half_rn(v1);
                }
            }
        }
        return;
    }

    // q or k columns: fused L2-normalize (+ scale*log2e for q)
    const int h = cbase >> 5;
    float hsc = 1.0f;
    if (is_q) hsc = __expf(fminf(ls[h], LOGIT_MAX)) * LOG2E;

#pragma unroll
    for (int mf = 0; mf < 2; mf++) {
        const int rlo = row0 + wm * 32 + mf * 16 + (lane >> 2);
        float va[4][4];
        float ss0 = 0.f, ss1 = 0.f;
#pragma unroll
        for (int nt = 0; nt < 4; nt++) {
            const int cc = cbase + nt * 8 + (lane & 3) * 2;
            float b0 = 0.f, b1 = 0.f;
            if (is_q) { b0 = bias1[cc]; b1 = bias1[cc + 1]; }
            va[nt][0] = acc[mf][nt][0] + b0;
            va[nt][1] = acc[mf][nt][1] + b1;
            va[nt][2] = acc[mf][nt][2] + b0;
            va[nt][3] = acc[mf][nt][3] + b1;
            ss0 += va[nt][0] * va[nt][0] + va[nt][1] * va[nt][1];
            ss1 += va[nt][2] * va[nt][2] + va[nt][3] * va[nt][3];
        }
        ss0 += __shfl_xor_sync(0xffffffffu, ss0, 1);
        ss0 += __shfl_xor_sync(0xffffffffu, ss0, 2);
        ss1 += __shfl_xor_sync(0xffffffffu, ss1, 1);
        ss1 += __shfl_xor_sync(0xffffffffu, ss1, 2);
        const float inv0 = hsc / fmaxf(sqrtf(ss0), 1e-12f);
        const float inv1 = hsc / fmaxf(sqrtf(ss1), 1e-12f);

#pragma unroll
        for (int half_ = 0; half_ < 2; half_++) {
            const int r = rlo + half_ * 8;
            const int b = r >> 9, n = r & 511;
            const float inv = half_ ? inv1 : inv0;
            const size_t base = (((size_t)(b * HEADS + h) << 9) | n) * HD;
#pragma unroll
            for (int nt = 0; nt < 4; nt++) {
                const int d = nt * 8 + (lane & 3) * 2;
                const float v0 = va[nt][half_ * 2 + 0] * inv;
                const float v1 = va[nt][half_ * 2 + 1] * inv;
                __half* dst = is_q ? g_qh : g_kh;
                *(__half2*)&dst[base + d] = __floats2half2_rn(v0, v1);
            }
        }
    }
}

// ============================================================
// Output projection: BM=256, BN=64, BK=32, 2-stage, 1-term
// (R16 configuration). Dynamic smem 51200 B -> 2 CTAs/SM.
// ============================================================
#define PA_OFF 0                       // [2][256][40] halves
#define PB_OFF (2 * 256 * 40)          // [2][64][40]
#define PROJ_SMEM ((PB_OFF + 2 * 64 * 40) * 2)   // 51200 bytes

__global__ __launch_bounds__(256, 2)
void proj_kernel(const __half* __restrict__ Ag, const __half* __restrict__ Wg,
                 const float* __restrict__ bias, float* __restrict__ outf)
{
    extern __shared__ __half smx[];
    __half* Ahs = smx + PA_OFF;
    __half* Bhs = smx + PB_OFF;

    const int tid = threadIdx.x, w = tid >> 5, lane = tid & 31;
    const int wm = w >> 1, wn = w & 1;
    const int row0 = blockIdx.y * 256, col0 = blockIdx.x * 64;

    auto load_stage = [&](int s, int buf) {
        const int k0 = s * 32;
        __half* Ab = Ahs + buf * 256 * 40;
#pragma unroll
        for (int j = 0; j < 4; j++) {
            const int idx = j * 256 + tid;
            const int r = idx >> 2, c8 = (idx & 3) * 8;
            cpa16(&Ab[r * 40 + c8], &Ag[(size_t)(row0 + r) * C_DIM + k0 + c8]);
        }
        {
            const int r = tid >> 2, c8 = (tid & 3) * 8;
            cpa16(&Bhs[buf * 64 * 40 + r * 40 + c8], &Wg[(size_t)(col0 + r) * C_DIM + k0 + c8]);
        }
    };

    float acc[4][4][4] = {};

    load_stage(0, 0);
    cpa_commit();

    for (int s = 0; s < 6; s++) {
        const int buf = s & 1;
        if (s < 5) { load_stage(s + 1, buf ^ 1); cpa_commit(); cpa_wait1(); }
        else       { cpa_wait0(); }
        __syncthreads();

        __half* Ab = Ahs + buf * 256 * 40;
#pragma unroll
        for (int kf = 0; kf < 2; kf++) {
            unsigned ah[4][4];
#pragma unroll
            for (int mf = 0; mf < 4; mf++) {
                unsigned a = smem_u32(&Ab[(wm * 64 + mf * 16 + (lane & 15)) * 40 + kf * 16 + (lane >> 4) * 8]);
                ldsm4(ah[mf][0], ah[mf][1], ah[mf][2], ah[mf][3], a);
            }
            unsigned bh_[4][2];
#pragma unroll
            for (int nt2 = 0; nt2 < 2; nt2++) {
                const int rowb = wn * 32 + nt2 * 16 + ((lane >> 4) << 3) + (lane & 7);
                const int colb = kf * 16 + ((lane >> 3) & 1) * 8;
                unsigned r0, r1, r2, r3;
                ldsm4(r0, r1, r2, r3, smem_u32(&Bhs[buf * 64 * 40 + rowb * 40 + colb]));
                bh_[nt2 * 2][0] = r0; bh_[nt2 * 2][1] = r1;
                bh_[nt2 * 2 + 1][0] = r2; bh_[nt2 * 2 + 1][1] = r3;
            }
#pragma unroll
            for (int mf = 0; mf < 4; mf++)
#pragma unroll
                for (int nt = 0; nt < 4; nt++)
                    mma16816(acc[mf][nt], ah[mf][0], ah[mf][1], ah[mf][2], ah[mf][3], bh_[nt][0], bh_[nt][1]);
        }
        __syncthreads();
    }

#pragma unroll
    for (int mf = 0; mf < 4; mf++) {
        const int rlo = row0 + wm * 64 + mf * 16 + (lane >> 2);
#pragma unroll
        for (int nt = 0; nt < 4; nt++) {
            const int cc = col0 + wn * 32 + nt * 8 + (lane & 3) * 2;
#pragma unroll
            for (int half_ = 0; half_ < 2; half_++) {
                const int r = rlo + half_ * 8;
                float2 o = make_float2(acc[mf][nt][half_ * 2 + 0] + bias[cc],
                                       acc[mf][nt][half_ * 2 + 1] + bias[cc + 1]);
                *(float2*)&outf[(size_t)r * C_DIM + cc] = o;
            }
        }
    }
}

// ============================================================
// Attention per (b,h). 256 thr, 8 warps, 3 CTA/SM. (R9-proven)
// ============================================================
__device__ __forceinline__ unsigned kswz(int r, int cbytes) {
    return r * 64 + (cbytes ^ ((r & 6) * 8));
}

__global__ __launch_bounds__(256, 3)
void attn_kernel(const float* __restrict__ ls)
{
    extern __shared__ __half sm[];
    __half* Khs = sm;                    // 512 rows x 64B, swizzled
    __half* Vts = sm + 512 * 32;         // [32][520]

    const int bh = blockIdx.x;
    const int b = bh / HEADS, h = bh % HEADS;
    const int tid = threadIdx.x, w = tid >> 5, lane = tid & 31;

    const float bias2 = __expf(fminf(ls[h], LOGIT_MAX)) * LOG2E;

    const __half* kh = g_kh + (size_t)bh * SEQ * HD;
    const __half* vt = g_vt + (size_t)bh * HD * SEQ;

#pragma unroll
    for (int p = 0; p < 8; p++) {
        const int idx = p * 256 + tid;
        const int r = idx >> 2, cb = (idx & 3) * 16;
        *(uint4*)((char*)Khs + kswz(r, cb)) = *(const uint4*)&kh[r * HD + cb / 2];
    }
#pragma unroll
    for (int p = 0; p < 8; p++) {
        const int idx = p * 256 + tid;
        const int d = idx >> 6, c8 = (idx & 63) * 8;
        *(uint4*)&Vts[d * 520 + c8] = *(const uint4*)&vt[d * SEQ + c8];
    }
    __syncthreads();

    const __half* qh = g_qh + (size_t)bh * SEQ * HD;

    for (int mf = 0; mf < 4; mf++) {
        const int m0 = w * 64 + mf * 16;
        const int rlo = m0 + (lane >> 2);

        unsigned qhf[2][4];
#pragma unroll
        for (int kf = 0; kf < 2; kf++) {
            const int kb = kf * 16 + (lane & 3) * 2;
            qhf[kf][0] = *(const unsigned*)&qh[(size_t)rlo * HD + kb];
            qhf[kf][1] = *(const unsigned*)&qh[(size_t)(rlo + 8) * HD + kb];
            qhf[kf][2] = *(const unsigned*)&qh[(size_t)rlo * HD + kb + 8];
            qhf[kf][3] = *(const unsigned*)&qh[(size_t)(rlo + 8) * HD + kb + 8];
        }

        float O[4][4] = {};
        float l_lo = 0.f, l_hi = 0.f;

        for (int kc = 0; kc < 8; kc++) {
            float S[8][4] = {};
#pragma unroll
            for (int nt2 = 0; nt2 < 4; nt2++) {
                const int rowb = kc * 64 + nt2 * 16 + ((lane >> 4) << 3) + (lane & 7);
                const int colb2 = ((lane >> 3) & 1) * 16;
#pragma unroll
                for (int kf = 0; kf < 2; kf++) {
                    const unsigned off = kswz(rowb, kf * 32 + colb2);
                    unsigned kh0, kh1, kh2, kh3;
                    ldsm4(kh0, kh1, kh2, kh3, smem_u32((char*)Khs + off));
                    mma16816(S[nt2 * 2],     qhf[kf][0], qhf[kf][1], qhf[kf][2], qhf[kf][3], kh0, kh1);
                    mma16816(S[nt2 * 2 + 1], qhf[kf][0], qhf[kf][1], qhf[kf][2], qhf[kf][3], kh2, kh3);
                }
            }

#pragma unroll
            for (int nt = 0; nt < 8; nt++) {
                S[nt][0] = ex2(S[nt][0] - bias2);
                S[nt][1] = ex2(S[nt][1] - bias2);
                S[nt][2] = ex2(S[nt][2] - bias2);
                S[nt][3] = ex2(S[nt][3] - bias2);
                l_lo += S[nt][0] + S[nt][1];
                l_hi += S[nt][2] + S[nt][3];
            }

#pragma unroll
            for (int ks = 0; ks < 4; ks++) {
                const unsigned p0 = pack_h2(S[2 * ks][0], S[2 * ks][1]);
                const unsigned p1 = pack_h2(S[2 * ks][2], S[2 * ks][3]);
                const unsigned p2 = pack_h2(S[2 * ks + 1][0], S[2 * ks + 1][1]);
                const unsigned p3 = pack_h2(S[2 * ks + 1][2], S[2 * ks + 1][3]);
#pragma unroll
                for (int dt2 = 0; dt2 < 2; dt2++) {
                    const int rowd = dt2 * 16 + ((lane >> 4) << 3) + (lane & 7);
                    const int colk = kc * 64 + ks * 16 + ((lane >> 3) & 1) * 8;
                    unsigned v0, v1, v2, v3;
                    ldsm4(v0, v1, v2, v3, smem_u32(&Vts[rowd * 520 + colk]));
                    mma16816(O[dt2 * 2],     p0, p1, p2, p3, v0, v1);
                    mma16816(O[dt2 * 2 + 1], p0, p1, p2, p3, v2, v3);
                }
            }
        }

        l_lo += __shfl_xor_sync(0xffffffffu, l_lo, 1);
        l_lo += __shfl_xor_sync(0xffffffffu, l_lo, 2);
        l_hi += __shfl_xor_sync(0xffffffffu, l_hi, 1);
        l_hi += __shfl_xor_sync(0xffffffffu, l_hi, 2);
        const float il_lo = 1.0f / l_lo, il_hi = 1.0f / l_hi;
#pragma unroll
        for (int dt = 0; dt < 4; dt++) {
            __half2 o_lo = __floats2half2_rn(O[dt][0] * il_lo, O[dt][1] * il_lo);
            __half2 o_hi = __floats2half2_rn(O[dt][2] * il_hi, O[dt][3] * il_hi);
            const size_t base = ((size_t)b * SEQ + rlo) * C_DIM + h * HD + dt * 8 + (lane & 3) * 2;
            *(__half2*)&g_attno[base] = o_lo;
            *(__half2*)&g_attno[base + (size_t)8 * C_DIM] = o_hi;
        }
    }
}

// ============================================================
// Launch
// ============================================================
extern "C" void kernel_launch(void* const* d_in, const int* in_sizes, int n_in,
                              void* d_out, int out_size)
{
    (void)in_sizes; (void)n_in; (void)out_size;
    const float* x1     = (const float*)d_in[0];
    const float* x2     = (const float*)d_in[1];
    const float* q_w    = (const float*)d_in[2];
    const float* q_b    = (const float*)d_in[3];
    const float* kv_w   = (const float*)d_in[4];
    const float* v_b    = (const float*)d_in[5];
    const float* ls     = (const float*)d_in[6];
    const float* proj_w = (const float*)d_in[7];
    const float* proj_b = (const float*)d_in[8];
    float* out = (float*)d_out;

    __half *x1h, *x2h, *wqh, *wkvh, *wph, *attno;
    cudaGetSymbolAddress((void**)&x1h,  g_x1h);
    cudaGetSymbolAddress((void**)&x2h,  g_x2h);
    cudaGetSymbolAddress((void**)&wqh,  g_wqh);
    cudaGetSymbolAddress((void**)&wkvh, g_wkvh);
    cudaGetSymbolAddress((void**)&wph,  g_wph);
    cudaGetSymbolAddress((void**)&attno, g_attno);

    prep_kernel<<<12360, 256>>>(x1, x2, q_w, kv_w, proj_w);

    // fused q + kv projections (all single-term fp16)
    qkv_kernel<<<dim3(9, MROWS / 128), 256>>>(x1h, x2h, wqh, wkvh, q_b, v_b, ls);

    const int smem_bytes = (512 * 32 + 32 * 520) * (int)sizeof(__half); // 66048
    cudaFuncSetAttribute(attn_kernel, cudaFuncAttributeMaxDynamicSharedMemorySize, smem_bytes);
    attn_kernel<<<BH, 256, smem_bytes>>>(ls);

    // output projection (BM=256)
    cudaFuncSetAttribute(proj_kernel, cudaFuncAttributeMaxDynamicSharedMemorySize, PROJ_SMEM);
    proj_kernel<<<dim3(3, MROWS / 256), 256, PROJ_SMEM>>>(attno, wph, proj_b, out);
}